// round 14
// baseline (speedup 1.0000x reference)
#include <cuda_runtime.h>
#include <cuda_fp16.h>
#include <cstdint>
#include <math.h>

// Problem dims
#define BATCH 8
#define SQL   2048
#define SKL   2048
#define DIM   1024

#define NELEM ((size_t)BATCH * SQL * DIM)      // 16.8M elements

// ---------------- device scratch (static) ----------------
// Interleaved pair layout "IL": logical row r of width W is stored as 2W halfs:
// for even col c: [hi(c), hi(c+1), lo(c), lo(c+1)] at half offset r*2W + 2c.
__device__ __half g_qI[2*NELEM], g_kI[2*NELEM];     // split q/k, interleaved
__device__ __half g_v0[NELEM];                      // V input single fp16
__device__ __half g_WqI[2*DIM*DIM], g_WkI[2*DIM*DIM]; // WT split, interleaved [N][K]
__device__ __half g_Wv0[DIM*DIM];                   // WvT single fp16
__device__ __half g_QpI[2*NELEM], g_KpI[2*NELEM];   // projections, interleaved
__device__ __half g_Vp0[NELEM];                     // single fp16 V
__device__ __half g_S16[(size_t)BATCH * SQL * SKL]; // tile-shifted scores (fp16)
__device__ float  g_Tmax[(size_t)BATCH * SQL * 16]; // per-row per-tile max (f32)
__device__ __half g_P0[(size_t)BATCH * SQL * SKL];  // softmax P (single fp16)
__device__ float  g_maskf[BATCH * SKL];
__device__ int    g_mask_mode;

// ---------------- small helpers ----------------
__device__ __forceinline__ uint32_t smem_u32(const void* p) {
    uint32_t a;
    asm("{ .reg .u64 t; cvta.to.shared.u64 t, %1; cvt.u32.u64 %0, t; }" : "=r"(a) : "l"(p));
    return a;
}
__device__ __forceinline__ void cp16(uint32_t dst, const void* src) {
    asm volatile("cp.async.cg.shared.global [%0], [%1], 16;" :: "r"(dst), "l"(src) : "memory");
}
__device__ __forceinline__ void cp_commit() {
    asm volatile("cp.async.commit_group;" ::: "memory");
}
template<int N> __device__ __forceinline__ void cp_wait() {
    asm volatile("cp.async.wait_group %0;" :: "n"(N) : "memory");
}
// mma.sync m16n8k16 f16 -> f32 accum
__device__ __forceinline__ void mma16(float* c, const uint32_t* a, const uint32_t* b) {
    asm volatile(
        "mma.sync.aligned.m16n8k16.row.col.f32.f16.f16.f32 "
        "{%0,%1,%2,%3}, {%4,%5,%6,%7}, {%8,%9}, {%0,%1,%2,%3};"
        : "+f"(c[0]), "+f"(c[1]), "+f"(c[2]), "+f"(c[3])
        : "r"(a[0]), "r"(a[1]), "r"(a[2]), "r"(a[3]), "r"(b[0]), "r"(b[1]));
}
__device__ __forceinline__ uint32_t lds32(const char* smem, int off) {
    return *(const uint32_t*)(smem + off);
}
// 64-bit shared load: fetches {hi,lo} pair regs in one instruction
__device__ __forceinline__ void lds64(uint32_t& x, uint32_t& y, const char* smem, int off) {
    uint2 v = *(const uint2*)(smem + off);
    x = v.x; y = v.y;
}
__device__ __forceinline__ uint32_t lds16x2(const char* smem, int off_lo, int off_hi) {
    uint32_t lo = *(const uint16_t*)(smem + off_lo);
    uint32_t hi = *(const uint16_t*)(smem + off_hi);
    return lo | (hi << 16);
}
// float <-> monotonic unsigned encoding (for atomicMax on floats incl. negatives)
__device__ __forceinline__ unsigned f2o(float f) {
    unsigned u = __float_as_uint(f);
    return (u & 0x80000000u) ? ~u : (u | 0x80000000u);
}
__device__ __forceinline__ float o2f(unsigned u) {
    return (u & 0x80000000u) ? __uint_as_float(u & 0x7FFFFFFFu) : __uint_as_float(~u);
}

// ---------------- mask dtype sniffing (verified R1) ----------------
__global__ void detect_mask_kernel(const unsigned int* __restrict__ w)
{
    __shared__ unsigned int f;
    if (threadIdx.x == 0) f = 0u;
    __syncthreads();
    unsigned int loc = 0u;
    for (int i = threadIdx.x; i < 4096; i += 256) {
        unsigned int x = w[i];
        if (x == 0x3F803F80u || x == 0x00003F80u) loc |= 8u;
        if (x == 0x3F800000u)                     loc |= 4u;
        if (x > 1u)                               loc |= 2u;
    }
    atomicOr(&f, loc);
    __syncthreads();
    if (threadIdx.x == 0) {
        unsigned int ff = f;
        g_mask_mode = (ff & 8u) ? 3 : (ff & 4u) ? 2 : (ff & 2u) ? 1 : 0;
    }
}
__global__ void convert_mask_kernel(const void* __restrict__ m, int n)
{
    int i = blockIdx.x * blockDim.x + threadIdx.x;
    if (i >= n) return;
    int mode = g_mask_mode;
    float v;
    if (mode == 0)      v = (float)((const int*)m)[i];
    else if (mode == 1) v = (float)((const unsigned char*)m)[i];
    else if (mode == 2) v = ((const float*)m)[i];
    else {
        unsigned short h = ((const unsigned short*)m)[i];
        v = __uint_as_float(((unsigned int)h) << 16);
    }
    g_maskf[i] = v;
}

// ---------------- split q,k -> interleaved pair buffers (one launch) ----------------
__global__ __launch_bounds__(256)
void split2_kernel(const float4* __restrict__ sq, const float4* __restrict__ sk,
                   uint2* __restrict__ qI, uint2* __restrict__ kI, int n4)
{
    int i = blockIdx.x * blockDim.x + threadIdx.x;
    if (i >= n4) return;
    const float4* src = blockIdx.y ? sk : sq;
    uint2* dst = blockIdx.y ? kI : qI;
    float4 x = src[i];
    __half a0 = __float2half_rn(x.x); __half b0 = __float2half_rn(x.x - __half2float(a0));
    __half a1 = __float2half_rn(x.y); __half b1 = __float2half_rn(x.y - __half2float(a1));
    __half a2 = __float2half_rn(x.z); __half b2 = __float2half_rn(x.z - __half2float(a2));
    __half a3 = __float2half_rn(x.w); __half b3 = __float2half_rn(x.w - __half2float(a3));
    __half2 h01 = __halves2half2(a0, a1), l01 = __halves2half2(b0, b1);
    __half2 h23 = __halves2half2(a2, a3), l23 = __halves2half2(b2, b3);
    uint2 o0, o1;
    o0.x = *(uint32_t*)&h01; o0.y = *(uint32_t*)&l01;
    o1.x = *(uint32_t*)&h23; o1.y = *(uint32_t*)&l23;
    dst[2*i]     = o0;
    dst[2*i + 1] = o1;
}

// single fp16 convert (for V input)
__global__ __launch_bounds__(256)
void convert_half_kernel(const float4* __restrict__ src, __half2* __restrict__ h0, int n4)
{
    int i = blockIdx.x * blockDim.x + threadIdx.x;
    if (i >= n4) return;
    float4 x = src[i];
    h0[2*i]   = __halves2half2(__float2half_rn(x.x), __float2half_rn(x.y));
    h0[2*i+1] = __halves2half2(__float2half_rn(x.z), __float2half_rn(x.w));
}

// W [K,N] -> WT [N,K]: z=0,1 -> interleaved split (Wq,Wk); z=2 -> plain single (Wv)
__global__ __launch_bounds__(256)
void transpose_split3_kernel(const float* __restrict__ Wa, const float* __restrict__ Wb,
                             const float* __restrict__ Wc,
                             __half* __restrict__ AI, __half* __restrict__ BI,
                             __half* __restrict__ C0)
{
    const float* W = (blockIdx.z == 0) ? Wa : (blockIdx.z == 1) ? Wb : Wc;
    __shared__ float t[32][33];
    int n0 = blockIdx.x * 32, k0 = blockIdx.y * 32;
    int tx = threadIdx.x & 31, ty = threadIdx.x >> 5;
    for (int r = ty; r < 32; r += 8)
        t[r][tx] = W[(size_t)(k0 + r) * DIM + n0 + tx];
    __syncthreads();
    if (blockIdx.z < 2) {
        __half* TI = (blockIdx.z == 0) ? AI : BI;
        for (int r = ty; r < 32; r += 8) {
            float x = t[tx][r];
            __half h = __float2half_rn(x);
            int kk = k0 + tx;
            size_t o = (size_t)(n0 + r) * 2 * DIM + (size_t)(kk >> 1) * 4 + (kk & 1);
            TI[o] = h; TI[o + 2] = __float2half_rn(x - __half2float(h));
        }
    } else {
        for (int r = ty; r < 32; r += 8) {
            float x = t[tx][r];
            C0[(size_t)(n0 + r) * DIM + k0 + tx] = __float2half_rn(x);
        }
    }
}

// ------------- fp16 mma GEMM: 128x128 tile, Kc=32, 2-stage cp.async, 2 CTAs/SM ----
// MODE 0: C = A@B^T + bias   -> interleaved fp16 split write (Q&K proj merged, 3 prod, IL operands)
// MODE 1: C = tanh(A@B^T+b)  -> fp16 write  (V proj, single product, plain operands)
// MODE 2: C = A@B^T + mask   -> tile-shifted fp16 S + tile max (QK^T, 3 prod, IL operands)
// MODE 3: C = A0@B0 (B=[K][N]) -> f32 write (P@V, single product)
template<int MODE>
__global__ __launch_bounds__(256, 2)
void mma_gemm(const __half* __restrict__ Ah, const __half* __restrict__ Bh,
              const float* __restrict__ aux,
              void* __restrict__ out0v, void* __restrict__ out1v,
              int ldA, int ldB,
              long long sAz, long long sBz, long long sAuxz,
              int nK, int ldO, long long sOz)
{
    constexpr bool IL = (MODE == 0 || MODE == 2);   // interleaved split A and B, 3 products
    constexpr bool BK = (MODE == 3);                // B is [K][N]
    constexpr int  A_BYTES = IL ? 18432 : 10240;    // IL: 128 rows x 144 B
    constexpr int  B_BYTES = IL ? 18432 : (BK ? 8704 : 10240);
    constexpr int  STG     = A_BYTES + B_BYTES;

    extern __shared__ char sm[];
    const uint32_t sb = smem_u32(sm);
    const int tid = threadIdx.x;
    const int lid = tid & 31, wid = tid >> 5;
    const int wm = wid >> 2, wn = wid & 3;      // 2 x 4 warp grid, warp tile 64x32
    const int lx = lid & 3,  ly = lid >> 2;
    const int m0 = blockIdx.y * 128, n0 = blockIdx.x * 128, z = blockIdx.z;
    const int nst = nK / 32;

    const __half* Ag = Ah + (size_t)z * sAz;
    const __half* Bg = Bh + (size_t)z * sBz;
    const float*  auxz = aux + (size_t)z * sAuxz;

    float acc[4][4][4];
#pragma unroll
    for (int a = 0; a < 4; a++)
#pragma unroll
        for (int b = 0; b < 4; b++)
#pragma unroll
            for (int c = 0; c < 4; c++) acc[a][b][c] = 0.f;

    // ---- producer: fill stage SLOT st with k-chunk kt (32 k) ----
    auto issue = [&](int st, int kt) {
        uint32_t base = sb + (uint32_t)st * STG;
        uint32_t bb   = base + A_BYTES;
        if (IL) {
            // interleaved tiles: 128 rows x 8 chunks of 16 B (=2 col-pairs), pitch 144 B
#pragma unroll
            for (int i = 0; i < 4; i++) {
                int q = i * 256 + tid; int r = q >> 3, c = q & 7;
                uint32_t d = (uint32_t)(r * 144 + c * 16);
                cp16(base + d, Ag + (size_t)(m0 + r) * 2 * ldA + kt * 2 + c * 8);
                cp16(bb + d,   Bg + (size_t)(n0 + r) * 2 * ldB + kt * 2 + c * 8);
            }
        } else if (!BK) {
            // plain single tiles: 128 rows x 4 chunks, pitch 80 B
#pragma unroll
            for (int i = 0; i < 2; i++) {
                int q = i * 256 + tid; int r = q >> 2, c = q & 3;
                uint32_t d = (uint32_t)(r * 80 + c * 16);
                cp16(base + d, Ag + (size_t)(m0 + r) * ldA + kt + c * 8);
                cp16(bb + d,   Bg + (size_t)(n0 + r) * ldB + kt + c * 8);
            }
        } else {
            // A plain 80 B pitch; B [K][N]: 32 k-rows x 16 chunks, pitch 272 B
#pragma unroll
            for (int i = 0; i < 2; i++) {
                int q = i * 256 + tid; int r = q >> 2, c = q & 3;
                uint32_t d = (uint32_t)(r * 80 + c * 16);
                cp16(base + d, Ag + (size_t)(m0 + r) * ldA + kt + c * 8);
            }
#pragma unroll
            for (int i = 0; i < 2; i++) {
                int q = i * 256 + tid; int r = q >> 4, c = q & 15;
                uint32_t d = (uint32_t)(r * 272 + c * 16);
                cp16(bb + d, Bg + (size_t)(kt + r) * ldB + n0 + c * 8);
            }
        }
        cp_commit();
    };

    issue(0, 0); issue(1, 32);

    // per-thread row byte bases
    int rowA[4];
#pragma unroll
    for (int mt = 0; mt < 4; mt++) {
        int r = wm * 64 + mt * 16 + ly;
        rowA[mt] = IL ? (r * 144 + lx * 8) : (r * 80 + lx * 4);
    }
    int rowB[4];
#pragma unroll
    for (int nt = 0; nt < 4; nt++) {
        int r = wn * 32 + nt * 8 + ly;
        if (IL)       rowB[nt] = r * 144 + lx * 8;
        else if (!BK) rowB[nt] = r * 80 + lx * 4;
        else          rowB[nt] = r;                 // column index
    }

#pragma unroll 1
    for (int it = 0; it < nst; it++) {
        if (it + 1 < nst) cp_wait<1>();
        else              cp_wait<0>();
        __syncthreads();
        const char* S0 = sm + (it & 1) * STG;
        const char* At = S0;
        const char* Bt = S0 + A_BYTES;

#pragma unroll
        for (int ks = 0; ks < 2; ks++) {
            uint32_t a0[4][4], a1[4][4];
            uint32_t b0[4][2], b1[4][2];
            if (IL) {
                const int kbI = ks * 64;           // byte offset of k16 slice (8 pairs)
#pragma unroll
                for (int mt = 0; mt < 4; mt++) {
                    int o = rowA[mt] + kbI;
                    lds64(a0[mt][0], a1[mt][0], At, o);
                    lds64(a0[mt][1], a1[mt][1], At, o + 1152);
                    lds64(a0[mt][2], a1[mt][2], At, o + 32);
                    lds64(a0[mt][3], a1[mt][3], At, o + 1152 + 32);
                }
#pragma unroll
                for (int nt = 0; nt < 4; nt++) {
                    int o = rowB[nt] + kbI;
                    lds64(b0[nt][0], b1[nt][0], Bt, o);
                    lds64(b0[nt][1], b1[nt][1], Bt, o + 32);
                }
#pragma unroll
                for (int mt = 0; mt < 4; mt++)
#pragma unroll
                    for (int nt = 0; nt < 4; nt++) {
                        mma16(acc[mt][nt], a0[mt], b0[nt]);
                        mma16(acc[mt][nt], a0[mt], b1[nt]);
                        mma16(acc[mt][nt], a1[mt], b0[nt]);
                    }
            } else {
                const int kb = ks * 32;            // byte offset in plain 80 B tiles
#pragma unroll
                for (int mt = 0; mt < 4; mt++) {
                    int o = rowA[mt] + kb;
                    a0[mt][0] = lds32(At, o);        a0[mt][1] = lds32(At, o + 640);
                    a0[mt][2] = lds32(At, o + 16);   a0[mt][3] = lds32(At, o + 656);
                }
#pragma unroll
                for (int nt = 0; nt < 4; nt++) {
                    if (!BK) {
                        int o = rowB[nt] + kb;
                        b0[nt][0] = lds32(Bt, o); b0[nt][1] = lds32(Bt, o + 16);
                    } else {
                        int krow = (kb >> 1) + 2 * lx;   // k index = ks*16 + 2lx
                        int base0 = krow * 272 + rowB[nt] * 2;
                        b0[nt][0] = lds16x2(Bt, base0,        base0 + 272);
                        b0[nt][1] = lds16x2(Bt, base0 + 2176, base0 + 2448);
                    }
                }
#pragma unroll
                for (int mt = 0; mt < 4; mt++)
#pragma unroll
                    for (int nt = 0; nt < 4; nt++)
                        mma16(acc[mt][nt], a0[mt], b0[nt]);
            }
        }
        __syncthreads();
        if (it + 2 < nst) issue(it & 1, (it + 2) * 32);
    }

    // ---- epilogue ----
    if (MODE == 2) {
        __syncthreads();
        unsigned* rmax = (unsigned*)sm;
        if (tid < 128) rmax[tid] = 0u;     // f2o-encoded -inf lower bound
        __syncthreads();
#pragma unroll
        for (int mt = 0; mt < 4; mt++) {
#pragma unroll
            for (int hf = 0; hf < 2; hf++) {
                const int rl = wm * 64 + mt * 16 + ly + hf * 8;
                float mx = -INFINITY;
#pragma unroll
                for (int nt = 0; nt < 4; nt++) {
                    const int col = n0 + wn * 32 + nt * 8 + 2 * lx;
                    float x0 = acc[mt][nt][hf * 2 + 0] + auxz[col];
                    float x1 = acc[mt][nt][hf * 2 + 1] + auxz[col + 1];
                    mx = fmaxf(mx, fmaxf(x0, x1));
                }
                atomicMax(&rmax[rl], f2o(mx));
            }
        }
        __syncthreads();
        __half* S16o = (__half*)out0v;
        float*  Tmxo = (float*)out1v;
#pragma unroll
        for (int mt = 0; mt < 4; mt++) {
#pragma unroll
            for (int hf = 0; hf < 2; hf++) {
                const int rl = wm * 64 + mt * 16 + ly + hf * 8;
                const float m = o2f(rmax[rl]);
                const int gm = m0 + rl;
#pragma unroll
                for (int nt = 0; nt < 4; nt++) {
                    const int col = n0 + wn * 32 + nt * 8 + 2 * lx;
                    float x0 = acc[mt][nt][hf * 2 + 0] + auxz[col];
                    float x1 = acc[mt][nt][hf * 2 + 1] + auxz[col + 1];
                    *(__half2*)(S16o + (size_t)z * sOz + (size_t)gm * ldO + col) =
                        __floats2half2_rn(x0 - m, x1 - m);
                }
                if (wn == 0 && lx == 0)
                    Tmxo[((size_t)z * SQL + gm) * 16 + (n0 >> 7)] = m;
            }
        }
        return;
    }

#pragma unroll
    for (int mt = 0; mt < 4; mt++) {
#pragma unroll
        for (int hf = 0; hf < 2; hf++) {
            const int gm = m0 + wm * 64 + mt * 16 + ly + hf * 8;
#pragma unroll
            for (int nt = 0; nt < 4; nt++) {
                const int col = n0 + wn * 32 + nt * 8 + 2 * lx;
                float c0 = acc[mt][nt][hf * 2 + 0];
                float c1 = acc[mt][nt][hf * 2 + 1];
                if (MODE == 0) {
                    // interleaved split write: one 8B store per 2 cols
                    float x0 = c0 + auxz[col], x1 = c1 + auxz[col + 1];
                    __half h0 = __float2half_rn(x0), h1 = __float2half_rn(x1);
                    __half2 hh = __halves2half2(h0, h1);
                    __half2 ll = __halves2half2(__float2half_rn(x0 - __half2float(h0)),
                                                __float2half_rn(x1 - __half2float(h1)));
                    uint2 u; u.x = *(uint32_t*)&hh; u.y = *(uint32_t*)&ll;
                    *(uint2*)((__half*)out0v + (size_t)z * sOz +
                              (size_t)gm * 2 * ldO + 2 * col) = u;
                } else if (MODE == 1) {
                    float x0 = tanhf(c0 + auxz[col]), x1 = tanhf(c1 + auxz[col + 1]);
                    *(__half2*)((__half*)out0v + (size_t)gm * ldO + col) =
                        __halves2half2(__float2half_rn(x0), __float2half_rn(x1));
                } else {
                    *(float2*)((float*)out0v + (size_t)z * sOz + (size_t)gm * ldO + col) =
                        make_float2(c0, c1);
                }
            }
        }
    }
}

// ------------- softmax: read fp16 tile-shifted S + f32 tile max, write fp16 P -------------
__global__ __launch_bounds__(256)
void softmax_rows(const __half* __restrict__ S16, const float* __restrict__ Tmax,
                  __half* __restrict__ P0)
{
    const size_t row = blockIdx.x;
    const __half2* srow = (const __half2*)(S16 + row * SKL);
    __half2* prow = (__half2*)(P0 + row * SKL);
    const float* tmr = Tmax + row * 16;
    const int t = threadIdx.x;

    float m = -INFINITY;
#pragma unroll
    for (int i = 0; i < 16; i += 4) {
        float4 tv = *(const float4*)(tmr + i);
        m = fmaxf(m, fmaxf(fmaxf(tv.x, tv.y), fmaxf(tv.z, tv.w)));
    }

    const int tg = t >> 6;
    float e[4][2];
    float sum = 0.f;
#pragma unroll
    for (int i = 0; i < 4; i++) {
        float adj = tmr[tg + 4 * i] - m;
        __half2 sv = srow[t + i * 256];
        float s0 = __low2float(sv)  + adj;
        float s1 = __high2float(sv) + adj;
        e[i][0] = __expf(s0); e[i][1] = __expf(s1);
        sum += e[i][0] + e[i][1];
    }

#pragma unroll
    for (int o = 16; o > 0; o >>= 1) sum += __shfl_xor_sync(0xFFFFFFFFu, sum, o);
    __shared__ float red[8];
    if ((t & 31) == 0) red[t >> 5] = sum;
    __syncthreads();
    float tot = 0.f;
#pragma unroll
    for (int w = 0; w < 8; w++) tot += red[w];
    const float inv = 1.0f / tot;

#pragma unroll
    for (int i = 0; i < 4; i++)
        prow[t + i * 256] = __floats2half2_rn(e[i][0] * inv, e[i][1] * inv);
}

// ---------------- launch ----------------
extern "C" void kernel_launch(void* const* d_in, const int* in_sizes, int n_in,
                              void* d_out, int out_size)
{
    const float* q    = (const float*)d_in[0];
    const float* k    = (const float*)d_in[1];
    const float* v    = (const float*)d_in[2];
    const void*  mask = d_in[3];
    const float* Wq   = (const float*)d_in[4];
    const float* bq   = (const float*)d_in[5];
    const float* Wk   = (const float*)d_in[6];
    const float* bk   = (const float*)d_in[7];
    const float* Wv   = (const float*)d_in[8];
    const float* bvp  = (const float*)d_in[9];
    float* out        = (float*)d_out;

    __half *qI, *kI, *v0, *WqI, *WkI, *Wv0, *QpI, *KpI, *Vp0, *P0, *S16;
    float *Tmax, *maskf;
    cudaGetSymbolAddress((void**)&qI, g_qI);   cudaGetSymbolAddress((void**)&kI, g_kI);
    cudaGetSymbolAddress((void**)&v0, g_v0);
    cudaGetSymbolAddress((void**)&WqI, g_WqI); cudaGetSymbolAddress((void**)&WkI, g_WkI);
    cudaGetSymbolAddress((void**)&Wv0, g_Wv0);
    cudaGetSymbolAddress((void**)&QpI, g_QpI); cudaGetSymbolAddress((void**)&KpI, g_KpI);
    cudaGetSymbolAddress((void**)&Vp0, g_Vp0);
    cudaGetSymbolAddress((void**)&P0, g_P0);
    cudaGetSymbolAddress((void**)&S16, g_S16); cudaGetSymbolAddress((void**)&Tmax, g_Tmax);
    cudaGetSymbolAddress((void**)&maskf, g_maskf);

    // mask -> float
    detect_mask_kernel<<<1, 256>>>((const unsigned int*)mask);
    convert_mask_kernel<<<(BATCH * SKL + 255) / 256, 256>>>(mask, BATCH * SKL);

    // split q,k (one launch, interleaved out) + convert v
    {
        int n4 = (int)(NELEM / 4);
        int nb = (n4 + 255) / 256;
        dim3 g2(nb, 2);
        split2_kernel<<<g2, 256>>>((const float4*)q, (const float4*)k,
                                   (uint2*)qI, (uint2*)kI, n4);
        convert_half_kernel<<<nb, 256>>>((const float4*)v, (__half2*)v0, n4);
    }
    // transpose + split all three weights in one launch
    {
        dim3 g(DIM / 32, DIM / 32, 3);
        transpose_split3_kernel<<<g, 256>>>(Wq, Wk, Wv, WqI, WkI, Wv0);
    }

    const int SMEM02 = 2 * 36864;   // IL modes: 73728 B -> 2 CTAs/SM
    const int SMEM1  = 2 * 20480;   // mode 1:   40960 B
    const int SMEM3  = 2 * 18944;   // mode 3:   37888 B
    cudaFuncSetAttribute(mma_gemm<0>, cudaFuncAttributeMaxDynamicSharedMemorySize, SMEM02);
    cudaFuncSetAttribute(mma_gemm<1>, cudaFuncAttributeMaxDynamicSharedMemorySize, SMEM1);
    cudaFuncSetAttribute(mma_gemm<2>, cudaFuncAttributeMaxDynamicSharedMemorySize, SMEM02);
    cudaFuncSetAttribute(mma_gemm<3>, cudaFuncAttributeMaxDynamicSharedMemorySize, SMEM3);

    // Q & K projections MERGED (z=2), interleaved operands + outputs
    {
        dim3 grid(DIM / 128, (BATCH * SQL) / 128, 2);
        long long sAz   = (long long)(kI  - qI);
        long long sBz   = (long long)(WkI - WqI);
        long long sAuxz = (long long)(bk  - bq);
        long long sOz   = (long long)(KpI - QpI);
        mma_gemm<0><<<grid, 256, SMEM02>>>(qI, WqI, bq, QpI, nullptr,
                                           DIM, DIM, sAz, sBz, sAuxz,
                                           DIM, DIM, sOz);
    }
    // V projection: single product v0 @ Wv0^T
    {
        dim3 grid(DIM / 128, (BATCH * SQL) / 128, 1);
        mma_gemm<1><<<grid, 256, SMEM1>>>(v0, Wv0, bvp, Vp0, nullptr,
                                          DIM, DIM, 0, 0, 0,
                                          DIM, DIM, 0);
    }

    // S16 = tile-shifted fp16 (Qp @ Kp^T + mask), Tmax = per-row tile maxes
    {
        dim3 grid(SKL / 128, SQL / 128, BATCH);
        mma_gemm<2><<<grid, 256, SMEM02>>>(QpI, KpI, maskf, S16, Tmax,
                                           DIM, DIM,
                                           (long long)2 * SQL * DIM,
                                           (long long)2 * SKL * DIM,
                                           SKL,
                                           DIM, SKL, (long long)SQL * SKL);
    }

    // softmax rows -> single fp16 P
    softmax_rows<<<BATCH * SQL, 256>>>(S16, Tmax, P0);

    // out = P0 @ Vp0  (batched, single product)
    {
        dim3 grid(DIM / 128, SQL / 128, BATCH);
        mma_gemm<3><<<grid, 256, SMEM3>>>(P0, Vp0, nullptr, out, nullptr,
                                          SKL, DIM,
                                          (long long)SQL * SKL,
                                          (long long)SKL * DIM,
                                          0,
                                          SKL, DIM, (long long)SQL * DIM);
    }
}

// round 15
// speedup vs baseline: 1.1988x; 1.1988x over previous
#include <cuda_runtime.h>
#include <cuda_fp16.h>
#include <cstdint>
#include <math.h>

// Problem dims
#define BATCH 8
#define SQL   2048
#define SKL   2048
#define DIM   1024

#define NELEM ((size_t)BATCH * SQL * DIM)      // 16.8M elements

// ---------------- device scratch (static) ----------------
__device__ __half g_q0[NELEM], g_q1[NELEM];
__device__ __half g_k0[NELEM], g_k1[NELEM];
__device__ __half g_v0[NELEM];                      // V input single fp16
__device__ __half g_Wq0[DIM*DIM], g_Wq1[DIM*DIM];   // transposed [N][K]
__device__ __half g_Wk0[DIM*DIM], g_Wk1[DIM*DIM];
__device__ __half g_Wv0[DIM*DIM];                   // WvT single fp16
__device__ __half g_Qp0[NELEM], g_Qp1[NELEM];
__device__ __half g_Kp0[NELEM], g_Kp1[NELEM];
__device__ __half g_Vp0[NELEM];                     // single fp16 V
__device__ __half g_S16[(size_t)BATCH * SQL * SKL]; // tile-shifted scores (fp16)
__device__ float  g_Tmax[(size_t)BATCH * SQL * 16]; // per-row per-tile max (f32)
__device__ __half g_P0[(size_t)BATCH * SQL * SKL];  // softmax P (single fp16)
__device__ float  g_maskf[BATCH * SKL];
__device__ int    g_mask_mode;

// ---------------- small helpers ----------------
__device__ __forceinline__ uint32_t smem_u32(const void* p) {
    uint32_t a;
    asm("{ .reg .u64 t; cvta.to.shared.u64 t, %1; cvt.u32.u64 %0, t; }" : "=r"(a) : "l"(p));
    return a;
}
__device__ __forceinline__ void cp16(uint32_t dst, const void* src) {
    asm volatile("cp.async.cg.shared.global [%0], [%1], 16;" :: "r"(dst), "l"(src) : "memory");
}
__device__ __forceinline__ void cp_commit() {
    asm volatile("cp.async.commit_group;" ::: "memory");
}
template<int N> __device__ __forceinline__ void cp_wait() {
    asm volatile("cp.async.wait_group %0;" :: "n"(N) : "memory");
}
// mma.sync m16n8k16 f16 -> f32 accum
__device__ __forceinline__ void mma16(float* c, const uint32_t* a, const uint32_t* b) {
    asm volatile(
        "mma.sync.aligned.m16n8k16.row.col.f32.f16.f16.f32 "
        "{%0,%1,%2,%3}, {%4,%5,%6,%7}, {%8,%9}, {%0,%1,%2,%3};"
        : "+f"(c[0]), "+f"(c[1]), "+f"(c[2]), "+f"(c[3])
        : "r"(a[0]), "r"(a[1]), "r"(a[2]), "r"(a[3]), "r"(b[0]), "r"(b[1]));
}
__device__ __forceinline__ uint32_t lds32(const char* smem, int off) {
    return *(const uint32_t*)(smem + off);
}
__device__ __forceinline__ uint32_t lds16x2(const char* smem, int off_lo, int off_hi) {
    uint32_t lo = *(const uint16_t*)(smem + off_lo);
    uint32_t hi = *(const uint16_t*)(smem + off_hi);
    return lo | (hi << 16);
}
// float <-> monotonic unsigned encoding (for atomicMax on floats incl. negatives)
__device__ __forceinline__ unsigned f2o(float f) {
    unsigned u = __float_as_uint(f);
    return (u & 0x80000000u) ? ~u : (u | 0x80000000u);
}
__device__ __forceinline__ float o2f(unsigned u) {
    return (u & 0x80000000u) ? __uint_as_float(u & 0x7FFFFFFFu) : __uint_as_float(~u);
}

// ---------------- mask dtype sniffing (verified R1) ----------------
__global__ void detect_mask_kernel(const unsigned int* __restrict__ w)
{
    __shared__ unsigned int f;
    if (threadIdx.x == 0) f = 0u;
    __syncthreads();
    unsigned int loc = 0u;
    for (int i = threadIdx.x; i < 4096; i += 256) {
        unsigned int x = w[i];
        if (x == 0x3F803F80u || x == 0x00003F80u) loc |= 8u;
        if (x == 0x3F800000u)                     loc |= 4u;
        if (x > 1u)                               loc |= 2u;
    }
    atomicOr(&f, loc);
    __syncthreads();
    if (threadIdx.x == 0) {
        unsigned int ff = f;
        g_mask_mode = (ff & 8u) ? 3 : (ff & 4u) ? 2 : (ff & 2u) ? 1 : 0;
    }
}
__global__ void convert_mask_kernel(const void* __restrict__ m, int n)
{
    int i = blockIdx.x * blockDim.x + threadIdx.x;
    if (i >= n) return;
    int mode = g_mask_mode;
    float v;
    if (mode == 0)      v = (float)((const int*)m)[i];
    else if (mode == 1) v = (float)((const unsigned char*)m)[i];
    else if (mode == 2) v = ((const float*)m)[i];
    else {
        unsigned short h = ((const unsigned short*)m)[i];
        v = __uint_as_float(((unsigned int)h) << 16);
    }
    g_maskf[i] = v;
}

// ---------------- q/k split + v convert in ONE launch (y: 0=q split, 1=k split, 2=v cvt) --
__global__ __launch_bounds__(256)
void prep_inputs_kernel(const float4* __restrict__ sq, const float4* __restrict__ sk,
                        const float4* __restrict__ sv,
                        __half2* __restrict__ q0, __half2* __restrict__ q1,
                        __half2* __restrict__ k0, __half2* __restrict__ k1,
                        __half2* __restrict__ v0, int n4)
{
    int i = blockIdx.x * blockDim.x + threadIdx.x;
    if (i >= n4) return;
    if (blockIdx.y == 2) {
        float4 x = sv[i];
        v0[2*i]   = __halves2half2(__float2half_rn(x.x), __float2half_rn(x.y));
        v0[2*i+1] = __halves2half2(__float2half_rn(x.z), __float2half_rn(x.w));
        return;
    }
    const float4* src = blockIdx.y ? sk : sq;
    __half2* h0 = blockIdx.y ? k0 : q0;
    __half2* h1 = blockIdx.y ? k1 : q1;
    float4 x = src[i];
    __half a0 = __float2half_rn(x.x); __half b0 = __float2half_rn(x.x - __half2float(a0));
    __half a1 = __float2half_rn(x.y); __half b1 = __float2half_rn(x.y - __half2float(a1));
    __half a2 = __float2half_rn(x.z); __half b2 = __float2half_rn(x.z - __half2float(a2));
    __half a3 = __float2half_rn(x.w); __half b3 = __float2half_rn(x.w - __half2float(a3));
    h0[2*i]   = __halves2half2(a0, a1);
    h0[2*i+1] = __halves2half2(a2, a3);
    h1[2*i]   = __halves2half2(b0, b1);
    h1[2*i+1] = __halves2half2(b2, b3);
}

// W [K,N] -> WT [N,K]: z=0,1 -> split (Wq,Wk); z=2 -> plain single (Wv)
__global__ __launch_bounds__(256)
void transpose_split3_kernel(const float* __restrict__ Wa, const float* __restrict__ Wb,
                             const float* __restrict__ Wc,
                             __half* __restrict__ A0, __half* __restrict__ A1,
                             __half* __restrict__ B0, __half* __restrict__ B1,
                             __half* __restrict__ C0)
{
    const float* W = (blockIdx.z == 0) ? Wa : (blockIdx.z == 1) ? Wb : Wc;
    __shared__ float t[32][33];
    int n0 = blockIdx.x * 32, k0 = blockIdx.y * 32;
    int tx = threadIdx.x & 31, ty = threadIdx.x >> 5;
    for (int r = ty; r < 32; r += 8)
        t[r][tx] = W[(size_t)(k0 + r) * DIM + n0 + tx];
    __syncthreads();
    if (blockIdx.z < 2) {
        __half* T0 = (blockIdx.z == 0) ? A0 : B0;
        __half* T1 = (blockIdx.z == 0) ? A1 : B1;
        for (int r = ty; r < 32; r += 8) {
            float x = t[tx][r];
            __half h = __float2half_rn(x);
            size_t o = (size_t)(n0 + r) * DIM + k0 + tx;
            T0[o] = h; T1[o] = __float2half_rn(x - __half2float(h));
        }
    } else {
        for (int r = ty; r < 32; r += 8) {
            float x = t[tx][r];
            C0[(size_t)(n0 + r) * DIM + k0 + tx] = __float2half_rn(x);
        }
    }
}

// ------------- fp16 mma GEMM: 128x128 tile, Kc=32, 2-stage cp.async, 2 CTAs/SM ----
// MODE 0: C = A@B^T + bias      -> fp16 split write   (Q&K proj MERGED via z, 3 prod)
// MODE 1: C = tanh(A@B^T+bias)  -> fp16 write         (V proj, SINGLE product)
// MODE 2: C = A@B^T + mask      -> tile-shifted fp16 S + f32 tile max (QK^T, 3 prod)
// MODE 3: C = A0@B0 (B=[K][N])  -> f32 write          (P@V, single product)
template<int MODE>
__global__ __launch_bounds__(256, 2)
void mma_gemm(const __half* __restrict__ Ah, const __half* __restrict__ Al,
              const __half* __restrict__ Bh, const __half* __restrict__ Bl,
              const float* __restrict__ aux,
              void* __restrict__ out0v, void* __restrict__ out1v,
              int ldA, int ldB,
              long long sAz, long long sAlz, long long sBz, long long sBlz,
              long long sAuxz,
              int nK, int ldO, long long sOz, long long sO1z)
{
    constexpr bool BK     = (MODE == 3);                 // B is [K][N]
    constexpr bool SPLITA = (MODE == 0 || MODE == 2);
    constexpr bool SPLITB = (MODE == 0 || MODE == 2);
    constexpr int  OFF_B0 = SPLITA ? 20480 : 10240;
    constexpr int  STG    = BK ? (10240 + 8704)
                               : (OFF_B0 + (SPLITB ? 20480 : 10240));

    extern __shared__ char sm[];
    const uint32_t sb = smem_u32(sm);
    const int tid = threadIdx.x;
    const int lid = tid & 31, wid = tid >> 5;
    const int wm = wid >> 2, wn = wid & 3;      // 2 x 4 warp grid, warp tile 64x32
    const int lx = lid & 3,  ly = lid >> 2;
    const int m0 = blockIdx.y * 128, n0 = blockIdx.x * 128, z = blockIdx.z;
    const int nst = nK / 32;

    const __half* Agh = Ah + (size_t)z * sAz;
    const __half* Agl = Al + (size_t)z * sAlz;
    const __half* Bgh = Bh + (size_t)z * sBz;
    const __half* Bgl = Bl + (size_t)z * sBlz;
    const float*  auxz = aux + (size_t)z * sAuxz;

    float acc[4][4][4];
#pragma unroll
    for (int a = 0; a < 4; a++)
#pragma unroll
        for (int b = 0; b < 4; b++)
#pragma unroll
            for (int c = 0; c < 4; c++) acc[a][b][c] = 0.f;

    // ---- producer: fill stage SLOT st with k-chunk kt (32 k) ----
    auto issue = [&](int st, int kt) {
        uint32_t base = sb + (uint32_t)st * STG;
        // A tile(s): 128 rows x 4 chunks (16B = 8 halfs), row stride 80 B
#pragma unroll
        for (int i = 0; i < 2; i++) {
            int q = i * 256 + tid; int r = q >> 2, c = q & 3;
            uint32_t d = (uint32_t)(r * 80 + c * 16);
            cp16(base + d, Agh + (size_t)(m0 + r) * ldA + kt + c * 8);
            if (SPLITA) cp16(base + 10240 + d, Agl + (size_t)(m0 + r) * ldA + kt + c * 8);
        }
        uint32_t bb = base + OFF_B0;
        if (!BK) {
#pragma unroll
            for (int i = 0; i < 2; i++) {
                int q = i * 256 + tid; int r = q >> 2, c = q & 3;
                uint32_t d = (uint32_t)(r * 80 + c * 16);
                cp16(bb + d, Bgh + (size_t)(n0 + r) * ldB + kt + c * 8);
                if (SPLITB) cp16(bb + 10240 + d, Bgl + (size_t)(n0 + r) * ldB + kt + c * 8);
            }
        } else {
            // single B tile: 32 k-rows x 16 chunks, row stride 272 B
#pragma unroll
            for (int i = 0; i < 2; i++) {
                int q = i * 256 + tid; int r = q >> 4, c = q & 15;
                uint32_t d = (uint32_t)(r * 272 + c * 16);
                cp16(bb + d, Bgh + (size_t)(kt + r) * ldB + n0 + c * 8);
            }
        }
        cp_commit();
    };

    issue(0, 0); issue(1, 32);

    // per-thread A row byte bases
    int rowA[4];
#pragma unroll
    for (int mt = 0; mt < 4; mt++) rowA[mt] = (wm * 64 + mt * 16 + ly) * 80 + 4 * lx;
    int rowB[4];
#pragma unroll
    for (int nt = 0; nt < 4; nt++) {
        if (!BK) rowB[nt] = (wn * 32 + nt * 8 + ly) * 80 + 4 * lx;
        else     rowB[nt] = wn * 32 + nt * 8 + ly;   // column index
    }

#pragma unroll 1
    for (int it = 0; it < nst; it++) {
        if (it + 1 < nst) cp_wait<1>();
        else              cp_wait<0>();
        __syncthreads();
        const char* S0 = sm + (it & 1) * STG;
        const char* A0t = S0;
        const char* A1t = S0 + 10240;                  // SPLITA only
        const char* B0t = S0 + OFF_B0;
        const char* B1t = S0 + OFF_B0 + 10240;         // SPLITB only

#pragma unroll
        for (int ks = 0; ks < 2; ks++) {
            const int kb = ks * 32;                 // byte offset of k16 slice (16 halfs)
            uint32_t a0[4][4], a1[4][4];
#pragma unroll
            for (int mt = 0; mt < 4; mt++) {
                int o = rowA[mt] + kb;
                a0[mt][0] = lds32(A0t, o);        a0[mt][1] = lds32(A0t, o + 640);
                a0[mt][2] = lds32(A0t, o + 16);   a0[mt][3] = lds32(A0t, o + 656);
                if (SPLITA) {
                    a1[mt][0] = lds32(A1t, o);        a1[mt][1] = lds32(A1t, o + 640);
                    a1[mt][2] = lds32(A1t, o + 16);   a1[mt][3] = lds32(A1t, o + 656);
                }
            }
            uint32_t b0[4][2], b1[4][2];
#pragma unroll
            for (int nt = 0; nt < 4; nt++) {
                if (!BK) {
                    int o = rowB[nt] + kb;
                    b0[nt][0] = lds32(B0t, o); b0[nt][1] = lds32(B0t, o + 16);
                    if (SPLITB) {
                        b1[nt][0] = lds32(B1t, o); b1[nt][1] = lds32(B1t, o + 16);
                    }
                } else {
                    int krow = (kb >> 1) + 2 * lx;        // k index = ks*16 + 2lx
                    int base0 = krow * 272 + rowB[nt] * 2;
                    b0[nt][0] = lds16x2(B0t, base0,        base0 + 272);
                    b0[nt][1] = lds16x2(B0t, base0 + 2176, base0 + 2448);
                }
            }
#pragma unroll
            for (int mt = 0; mt < 4; mt++)
#pragma unroll
                for (int nt = 0; nt < 4; nt++) {
                    mma16(acc[mt][nt], a0[mt], b0[nt]);
                    if (SPLITB) mma16(acc[mt][nt], a0[mt], b1[nt]);
                    if (SPLITA) mma16(acc[mt][nt], a1[mt], b0[nt]);
                }
        }
        __syncthreads();
        if (it + 2 < nst) issue(it & 1, (it + 2) * 32);
    }

    // ---- epilogue ----
    if (MODE == 2) {
        // per-row (within CTA) tile max via smem atomicMax, then shifted fp16 store
        __syncthreads();
        unsigned* rmax = (unsigned*)sm;
        if (tid < 128) rmax[tid] = 0u;     // f2o-encoded -inf lower bound
        __syncthreads();
#pragma unroll
        for (int mt = 0; mt < 4; mt++) {
#pragma unroll
            for (int hf = 0; hf < 2; hf++) {
                const int rl = wm * 64 + mt * 16 + ly + hf * 8;
                float mx = -INFINITY;
#pragma unroll
                for (int nt = 0; nt < 4; nt++) {
                    const int col = n0 + wn * 32 + nt * 8 + 2 * lx;
                    float x0 = acc[mt][nt][hf * 2 + 0] + auxz[col];
                    float x1 = acc[mt][nt][hf * 2 + 1] + auxz[col + 1];
                    mx = fmaxf(mx, fmaxf(x0, x1));
                }
                atomicMax(&rmax[rl], f2o(mx));
            }
        }
        __syncthreads();
        __half* S16o = (__half*)out0v;
        float*  Tmxo = (float*)out1v;
#pragma unroll
        for (int mt = 0; mt < 4; mt++) {
#pragma unroll
            for (int hf = 0; hf < 2; hf++) {
                const int rl = wm * 64 + mt * 16 + ly + hf * 8;
                const float m = o2f(rmax[rl]);
                const int gm = m0 + rl;
#pragma unroll
                for (int nt = 0; nt < 4; nt++) {
                    const int col = n0 + wn * 32 + nt * 8 + 2 * lx;
                    float x0 = acc[mt][nt][hf * 2 + 0] + auxz[col];
                    float x1 = acc[mt][nt][hf * 2 + 1] + auxz[col + 1];
                    *(__half2*)(S16o + (size_t)z * sOz + (size_t)gm * ldO + col) =
                        __floats2half2_rn(x0 - m, x1 - m);
                }
                if (wn == 0 && lx == 0)
                    Tmxo[((size_t)z * SQL + gm) * 16 + (n0 >> 7)] = m;
            }
        }
        return;
    }

#pragma unroll
    for (int mt = 0; mt < 4; mt++) {
#pragma unroll
        for (int hf = 0; hf < 2; hf++) {
            const int gm = m0 + wm * 64 + mt * 16 + ly + hf * 8;
#pragma unroll
            for (int nt = 0; nt < 4; nt++) {
                const int col = n0 + wn * 32 + nt * 8 + 2 * lx;
                float c0 = acc[mt][nt][hf * 2 + 0];
                float c1 = acc[mt][nt][hf * 2 + 1];
                if (MODE == 0) {
                    float x0 = c0 + auxz[col], x1 = c1 + auxz[col + 1];
                    __half h0 = __float2half_rn(x0), h1 = __float2half_rn(x1);
                    __half l0 = __float2half_rn(x0 - __half2float(h0));
                    __half l1 = __float2half_rn(x1 - __half2float(h1));
                    *(__half2*)((__half*)out0v + (size_t)z * sOz + (size_t)gm * ldO + col) =
                        __halves2half2(h0, h1);
                    *(__half2*)((__half*)out1v + (size_t)z * sO1z + (size_t)gm * ldO + col) =
                        __halves2half2(l0, l1);
                } else if (MODE == 1) {
                    float x0 = tanhf(c0 + auxz[col]), x1 = tanhf(c1 + auxz[col + 1]);
                    *(__half2*)((__half*)out0v + (size_t)gm * ldO + col) =
                        __halves2half2(__float2half_rn(x0), __float2half_rn(x1));
                } else {
                    *(float2*)((float*)out0v + (size_t)z * sOz + (size_t)gm * ldO + col) =
                        make_float2(c0, c1);
                }
            }
        }
    }
}

// ------------- softmax: read fp16 tile-shifted S + f32 tile max, write fp16 P -------------
__global__ __launch_bounds__(256)
void softmax_rows(const __half* __restrict__ S16, const float* __restrict__ Tmax,
                  __half* __restrict__ P0)
{
    const size_t row = blockIdx.x;
    const __half2* srow = (const __half2*)(S16 + row * SKL);
    __half2* prow = (__half2*)(P0 + row * SKL);
    const float* tmr = Tmax + row * 16;
    const int t = threadIdx.x;

    float m = -INFINITY;
#pragma unroll
    for (int i = 0; i < 16; i += 4) {
        float4 tv = *(const float4*)(tmr + i);
        m = fmaxf(m, fmaxf(fmaxf(tv.x, tv.y), fmaxf(tv.z, tv.w)));
    }

    const int tg = t >> 6;
    float e[4][2];
    float sum = 0.f;
#pragma unroll
    for (int i = 0; i < 4; i++) {
        float adj = tmr[tg + 4 * i] - m;
        __half2 sv = srow[t + i * 256];
        float s0 = __low2float(sv)  + adj;
        float s1 = __high2float(sv) + adj;
        e[i][0] = __expf(s0); e[i][1] = __expf(s1);
        sum += e[i][0] + e[i][1];
    }

#pragma unroll
    for (int o = 16; o > 0; o >>= 1) sum += __shfl_xor_sync(0xFFFFFFFFu, sum, o);
    __shared__ float red[8];
    if ((t & 31) == 0) red[t >> 5] = sum;
    __syncthreads();
    float tot = 0.f;
#pragma unroll
    for (int w = 0; w < 8; w++) tot += red[w];
    const float inv = 1.0f / tot;

#pragma unroll
    for (int i = 0; i < 4; i++)
        prow[t + i * 256] = __floats2half2_rn(e[i][0] * inv, e[i][1] * inv);
}

// ---------------- launch ----------------
extern "C" void kernel_launch(void* const* d_in, const int* in_sizes, int n_in,
                              void* d_out, int out_size)
{
    const float* q    = (const float*)d_in[0];
    const float* k    = (const float*)d_in[1];
    const float* v    = (const float*)d_in[2];
    const void*  mask = d_in[3];
    const float* Wq   = (const float*)d_in[4];
    const float* bq   = (const float*)d_in[5];
    const float* Wk   = (const float*)d_in[6];
    const float* bk   = (const float*)d_in[7];
    const float* Wv   = (const float*)d_in[8];
    const float* bvp  = (const float*)d_in[9];
    float* out        = (float*)d_out;

    __half *q0, *q1, *k0, *k1, *v0;
    __half *Wq0, *Wq1, *Wk0, *Wk1, *Wv0;
    __half *Qp0, *Qp1, *Kp0, *Kp1, *Vp0, *P0, *S16;
    float *Tmax, *maskf;
    cudaGetSymbolAddress((void**)&q0, g_q0);   cudaGetSymbolAddress((void**)&q1, g_q1);
    cudaGetSymbolAddress((void**)&k0, g_k0);   cudaGetSymbolAddress((void**)&k1, g_k1);
    cudaGetSymbolAddress((void**)&v0, g_v0);
    cudaGetSymbolAddress((void**)&Wq0, g_Wq0); cudaGetSymbolAddress((void**)&Wq1, g_Wq1);
    cudaGetSymbolAddress((void**)&Wk0, g_Wk0); cudaGetSymbolAddress((void**)&Wk1, g_Wk1);
    cudaGetSymbolAddress((void**)&Wv0, g_Wv0);
    cudaGetSymbolAddress((void**)&Qp0, g_Qp0); cudaGetSymbolAddress((void**)&Qp1, g_Qp1);
    cudaGetSymbolAddress((void**)&Kp0, g_Kp0); cudaGetSymbolAddress((void**)&Kp1, g_Kp1);
    cudaGetSymbolAddress((void**)&Vp0, g_Vp0);
    cudaGetSymbolAddress((void**)&P0, g_P0);
    cudaGetSymbolAddress((void**)&S16, g_S16); cudaGetSymbolAddress((void**)&Tmax, g_Tmax);
    cudaGetSymbolAddress((void**)&maskf, g_maskf);

    // mask -> float
    detect_mask_kernel<<<1, 256>>>((const unsigned int*)mask);
    convert_mask_kernel<<<(BATCH * SKL + 255) / 256, 256>>>(mask, BATCH * SKL);

    // q/k split + v convert, single launch
    {
        int n4 = (int)(NELEM / 4);
        int nb = (n4 + 255) / 256;
        dim3 g3(nb, 3);
        prep_inputs_kernel<<<g3, 256>>>((const float4*)q, (const float4*)k,
                                        (const float4*)v,
                                        (__half2*)q0, (__half2*)q1,
                                        (__half2*)k0, (__half2*)k1,
                                        (__half2*)v0, n4);
    }
    // transpose + split all three weights in one launch
    {
        dim3 g(DIM / 32, DIM / 32, 3);
        transpose_split3_kernel<<<g, 256>>>(Wq, Wk, Wv, Wq0, Wq1, Wk0, Wk1, Wv0);
    }

    const int SMEM02 = 2 * 40960;   // modes 0,2: 81920 B -> 2 CTAs/SM
    const int SMEM1  = 2 * 20480;   // mode 1:   40960 B
    const int SMEM3  = 2 * 18944;   // mode 3:   37888 B
    cudaFuncSetAttribute(mma_gemm<0>, cudaFuncAttributeMaxDynamicSharedMemorySize, SMEM02);
    cudaFuncSetAttribute(mma_gemm<1>, cudaFuncAttributeMaxDynamicSharedMemorySize, SMEM1);
    cudaFuncSetAttribute(mma_gemm<2>, cudaFuncAttributeMaxDynamicSharedMemorySize, SMEM02);
    cudaFuncSetAttribute(mma_gemm<3>, cudaFuncAttributeMaxDynamicSharedMemorySize, SMEM3);

    // Q & K projections MERGED: grid z=2 selects problem instance via pointer-diff strides
    {
        dim3 grid(DIM / 128, (BATCH * SQL) / 128, 2);
        long long sAz   = (long long)(k0  - q0);
        long long sAlz  = (long long)(k1  - q1);
        long long sBz   = (long long)(Wk0 - Wq0);
        long long sBlz  = (long long)(Wk1 - Wq1);
        long long sAuxz = (long long)(bk  - bq);
        long long sOz   = (long long)(Kp0 - Qp0);
        long long sO1z  = (long long)(Kp1 - Qp1);
        mma_gemm<0><<<grid, 256, SMEM02>>>(q0, q1, Wq0, Wq1, bq, Qp0, Qp1,
                                           DIM, DIM,
                                           sAz, sAlz, sBz, sBlz, sAuxz,
                                           DIM, DIM, sOz, sO1z);
    }
    // V projection: single product v0 @ Wv0^T
    {
        dim3 grid(DIM / 128, (BATCH * SQL) / 128, 1);
        mma_gemm<1><<<grid, 256, SMEM1>>>(v0, v0, Wv0, Wv0, bvp, Vp0, nullptr,
                                          DIM, DIM, 0, 0, 0, 0, 0,
                                          DIM, DIM, 0, 0);
    }

    // S16 = tile-shifted fp16 (Qp @ Kp^T + mask), Tmax = per-row tile maxes
    {
        dim3 grid(SKL / 128, SQL / 128, BATCH);
        mma_gemm<2><<<grid, 256, SMEM02>>>(Qp0, Qp1, Kp0, Kp1, maskf, S16, Tmax,
                                           DIM, DIM,
                                           (long long)SQL * DIM, (long long)SQL * DIM,
                                           (long long)SKL * DIM, (long long)SKL * DIM,
                                           SKL,
                                           DIM, SKL, (long long)SQL * SKL, 0);
    }

    // softmax rows -> single fp16 P
    softmax_rows<<<BATCH * SQL, 256>>>(S16, Tmax, P0);

    // out = P0 @ Vp0  (batched, single product)
    {
        dim3 grid(DIM / 128, SQL / 128, BATCH);
        mma_gemm<3><<<grid, 256, SMEM3>>>(P0, P0, Vp0, Vp0, nullptr, out, nullptr,
                                          SKL, DIM,
                                          (long long)SQL * SKL, (long long)SQL * SKL,
                                          (long long)SKL * DIM, (long long)SKL * DIM,
                                          0,
                                          SKL, DIM, (long long)SQL * DIM, 0);
    }
}

// round 16
// speedup vs baseline: 1.2008x; 1.0017x over previous
#include <cuda_runtime.h>
#include <cuda_fp16.h>
#include <cstdint>
#include <math.h>

// Problem dims
#define BATCH 8
#define SQL   2048
#define SKL   2048
#define DIM   1024

#define NELEM ((size_t)BATCH * SQL * DIM)      // 16.8M elements

// ---------------- device scratch (static) ----------------
__device__ __half g_q0[NELEM], g_q1[NELEM];
__device__ __half g_k0[NELEM], g_k1[NELEM];
__device__ __half g_v0[NELEM];                      // V input single fp16
__device__ __half g_Wq0[DIM*DIM], g_Wq1[DIM*DIM];   // transposed [N][K]
__device__ __half g_Wk0[DIM*DIM], g_Wk1[DIM*DIM];
__device__ __half g_Wv0[DIM*DIM];                   // WvT single fp16
__device__ __half g_Qp0[NELEM], g_Qp1[NELEM];
__device__ __half g_Kp0[NELEM], g_Kp1[NELEM];
__device__ __half g_Vp0[NELEM];                     // single fp16 V
__device__ __half g_S16[(size_t)BATCH * SQL * SKL]; // tile-shifted scores (fp16)
__device__ float  g_Tmax[(size_t)BATCH * SQL * 16]; // per-row per-tile max (f32)
__device__ __half g_P0[(size_t)BATCH * SQL * SKL];  // softmax P (single fp16)
__device__ float  g_maskf[BATCH * SKL];
__device__ int    g_mask_mode;

// ---------------- small helpers ----------------
__device__ __forceinline__ uint32_t smem_u32(const void* p) {
    uint32_t a;
    asm("{ .reg .u64 t; cvta.to.shared.u64 t, %1; cvt.u32.u64 %0, t; }" : "=r"(a) : "l"(p));
    return a;
}
__device__ __forceinline__ void cp16(uint32_t dst, const void* src) {
    asm volatile("cp.async.cg.shared.global [%0], [%1], 16;" :: "r"(dst), "l"(src) : "memory");
}
__device__ __forceinline__ void cp_commit() {
    asm volatile("cp.async.commit_group;" ::: "memory");
}
template<int N> __device__ __forceinline__ void cp_wait() {
    asm volatile("cp.async.wait_group %0;" :: "n"(N) : "memory");
}
// mma.sync m16n8k16 f16 -> f32 accum
__device__ __forceinline__ void mma16(float* c, const uint32_t* a, const uint32_t* b) {
    asm volatile(
        "mma.sync.aligned.m16n8k16.row.col.f32.f16.f16.f32 "
        "{%0,%1,%2,%3}, {%4,%5,%6,%7}, {%8,%9}, {%0,%1,%2,%3};"
        : "+f"(c[0]), "+f"(c[1]), "+f"(c[2]), "+f"(c[3])
        : "r"(a[0]), "r"(a[1]), "r"(a[2]), "r"(a[3]), "r"(b[0]), "r"(b[1]));
}
__device__ __forceinline__ uint32_t lds32(const char* smem, int off) {
    return *(const uint32_t*)(smem + off);
}
__device__ __forceinline__ uint32_t lds16x2(const char* smem, int off_lo, int off_hi) {
    uint32_t lo = *(const uint16_t*)(smem + off_lo);
    uint32_t hi = *(const uint16_t*)(smem + off_hi);
    return lo | (hi << 16);
}
// float <-> monotonic unsigned encoding (for atomicMax on floats incl. negatives)
__device__ __forceinline__ unsigned f2o(float f) {
    unsigned u = __float_as_uint(f);
    return (u & 0x80000000u) ? ~u : (u | 0x80000000u);
}
__device__ __forceinline__ float o2f(unsigned u) {
    return (u & 0x80000000u) ? __uint_as_float(u & 0x7FFFFFFFu) : __uint_as_float(~u);
}
__device__ __forceinline__ uint32_t h2u(__half2 h) { return *(uint32_t*)&h; }

// ---------------- mask dtype sniffing (verified R1) ----------------
__global__ void detect_mask_kernel(const unsigned int* __restrict__ w)
{
    __shared__ unsigned int f;
    if (threadIdx.x == 0) f = 0u;
    __syncthreads();
    unsigned int loc = 0u;
    for (int i = threadIdx.x; i < 4096; i += 256) {
        unsigned int x = w[i];
        if (x == 0x3F803F80u || x == 0x00003F80u) loc |= 8u;
        if (x == 0x3F800000u)                     loc |= 4u;
        if (x > 1u)                               loc |= 2u;
    }
    atomicOr(&f, loc);
    __syncthreads();
    if (threadIdx.x == 0) {
        unsigned int ff = f;
        g_mask_mode = (ff & 8u) ? 3 : (ff & 4u) ? 2 : (ff & 2u) ? 1 : 0;
    }
}
__global__ void convert_mask_kernel(const void* __restrict__ m, int n)
{
    int i = blockIdx.x * blockDim.x + threadIdx.x;
    if (i >= n) return;
    int mode = g_mask_mode;
    float v;
    if (mode == 0)      v = (float)((const int*)m)[i];
    else if (mode == 1) v = (float)((const unsigned char*)m)[i];
    else if (mode == 2) v = ((const float*)m)[i];
    else {
        unsigned short h = ((const unsigned short*)m)[i];
        v = __uint_as_float(((unsigned int)h) << 16);
    }
    g_maskf[i] = v;
}

// ---------------- q/k split + v convert in ONE launch, packed uint2 stores ----------------
__global__ __launch_bounds__(256)
void prep_inputs_kernel(const float4* __restrict__ sq, const float4* __restrict__ sk,
                        const float4* __restrict__ sv,
                        uint2* __restrict__ q0, uint2* __restrict__ q1,
                        uint2* __restrict__ k0, uint2* __restrict__ k1,
                        uint2* __restrict__ v0, int n4)
{
    int i = blockIdx.x * blockDim.x + threadIdx.x;
    if (i >= n4) return;
    if (blockIdx.y == 2) {
        float4 x = sv[i];
        uint2 o;
        o.x = h2u(__halves2half2(__float2half_rn(x.x), __float2half_rn(x.y)));
        o.y = h2u(__halves2half2(__float2half_rn(x.z), __float2half_rn(x.w)));
        v0[i] = o;
        return;
    }
    const float4* src = blockIdx.y ? sk : sq;
    uint2* h0 = blockIdx.y ? k0 : q0;
    uint2* h1 = blockIdx.y ? k1 : q1;
    float4 x = src[i];
    __half a0 = __float2half_rn(x.x); __half b0 = __float2half_rn(x.x - __half2float(a0));
    __half a1 = __float2half_rn(x.y); __half b1 = __float2half_rn(x.y - __half2float(a1));
    __half a2 = __float2half_rn(x.z); __half b2 = __float2half_rn(x.z - __half2float(a2));
    __half a3 = __float2half_rn(x.w); __half b3 = __float2half_rn(x.w - __half2float(a3));
    uint2 oh, ol;
    oh.x = h2u(__halves2half2(a0, a1)); oh.y = h2u(__halves2half2(a2, a3));
    ol.x = h2u(__halves2half2(b0, b1)); ol.y = h2u(__halves2half2(b2, b3));
    h0[i] = oh;
    h1[i] = ol;
}

// W [K,N] -> WT [N,K]: z=0,1 -> split (Wq,Wk); z=2 -> plain single (Wv)
__global__ __launch_bounds__(256)
void transpose_split3_kernel(const float* __restrict__ Wa, const float* __restrict__ Wb,
                             const float* __restrict__ Wc,
                             __half* __restrict__ A0, __half* __restrict__ A1,
                             __half* __restrict__ B0, __half* __restrict__ B1,
                             __half* __restrict__ C0)
{
    const float* W = (blockIdx.z == 0) ? Wa : (blockIdx.z == 1) ? Wb : Wc;
    __shared__ float t[32][33];
    int n0 = blockIdx.x * 32, k0 = blockIdx.y * 32;
    int tx = threadIdx.x & 31, ty = threadIdx.x >> 5;
    for (int r = ty; r < 32; r += 8)
        t[r][tx] = W[(size_t)(k0 + r) * DIM + n0 + tx];
    __syncthreads();
    if (blockIdx.z < 2) {
        __half* T0 = (blockIdx.z == 0) ? A0 : B0;
        __half* T1 = (blockIdx.z == 0) ? A1 : B1;
        for (int r = ty; r < 32; r += 8) {
            float x = t[tx][r];
            __half h = __float2half_rn(x);
            size_t o = (size_t)(n0 + r) * DIM + k0 + tx;
            T0[o] = h; T1[o] = __float2half_rn(x - __half2float(h));
        }
    } else {
        for (int r = ty; r < 32; r += 8) {
            float x = t[tx][r];
            C0[(size_t)(n0 + r) * DIM + k0 + tx] = __float2half_rn(x);
        }
    }
}

// ------------- fp16 mma GEMM: 128x128 tile, Kc=32, 2-stage cp.async, 2 CTAs/SM ----
// MODE 0: C = A@B^T + bias      -> fp16 split write   (Q&K proj MERGED via z, 3 prod)
// MODE 1: C = tanh(A@B^T+bias)  -> fp16 write         (V proj, SINGLE product)
// MODE 2: C = A@B^T + mask      -> tile-shifted fp16 S + f32 tile max (QK^T, 3 prod)
// MODE 3: C = A0@B0 (B=[K][N])  -> f32 write          (P@V, single product)
template<int MODE>
__global__ __launch_bounds__(256, 2)
void mma_gemm(const __half* __restrict__ Ah, const __half* __restrict__ Al,
              const __half* __restrict__ Bh, const __half* __restrict__ Bl,
              const float* __restrict__ aux,
              void* __restrict__ out0v, void* __restrict__ out1v,
              int ldA, int ldB,
              long long sAz, long long sAlz, long long sBz, long long sBlz,
              long long sAuxz,
              int nK, int ldO, long long sOz, long long sO1z)
{
    constexpr bool BK     = (MODE == 3);                 // B is [K][N]
    constexpr bool SPLITA = (MODE == 0 || MODE == 2);
    constexpr bool SPLITB = (MODE == 0 || MODE == 2);
    constexpr int  OFF_B0 = SPLITA ? 20480 : 10240;
    constexpr int  STG    = BK ? (10240 + 8704)
                               : (OFF_B0 + (SPLITB ? 20480 : 10240));

    extern __shared__ char sm[];
    const uint32_t sb = smem_u32(sm);
    const int tid = threadIdx.x;
    const int lid = tid & 31, wid = tid >> 5;
    const int wm = wid >> 2, wn = wid & 3;      // 2 x 4 warp grid, warp tile 64x32
    const int lx = lid & 3,  ly = lid >> 2;
    const int m0 = blockIdx.y * 128, n0 = blockIdx.x * 128, z = blockIdx.z;
    const int nst = nK / 32;

    const __half* Agh = Ah + (size_t)z * sAz;
    const __half* Agl = Al + (size_t)z * sAlz;
    const __half* Bgh = Bh + (size_t)z * sBz;
    const __half* Bgl = Bl + (size_t)z * sBlz;
    const float*  auxz = aux + (size_t)z * sAuxz;

    float acc[4][4][4];
#pragma unroll
    for (int a = 0; a < 4; a++)
#pragma unroll
        for (int b = 0; b < 4; b++)
#pragma unroll
            for (int c = 0; c < 4; c++) acc[a][b][c] = 0.f;

    // ---- producer: fill stage SLOT st with k-chunk kt (32 k) ----
    auto issue = [&](int st, int kt) {
        uint32_t base = sb + (uint32_t)st * STG;
        // A tile(s): 128 rows x 4 chunks (16B = 8 halfs), row stride 80 B
#pragma unroll
        for (int i = 0; i < 2; i++) {
            int q = i * 256 + tid; int r = q >> 2, c = q & 3;
            uint32_t d = (uint32_t)(r * 80 + c * 16);
            cp16(base + d, Agh + (size_t)(m0 + r) * ldA + kt + c * 8);
            if (SPLITA) cp16(base + 10240 + d, Agl + (size_t)(m0 + r) * ldA + kt + c * 8);
        }
        uint32_t bb = base + OFF_B0;
        if (!BK) {
#pragma unroll
            for (int i = 0; i < 2; i++) {
                int q = i * 256 + tid; int r = q >> 2, c = q & 3;
                uint32_t d = (uint32_t)(r * 80 + c * 16);
                cp16(bb + d, Bgh + (size_t)(n0 + r) * ldB + kt + c * 8);
                if (SPLITB) cp16(bb + 10240 + d, Bgl + (size_t)(n0 + r) * ldB + kt + c * 8);
            }
        } else {
            // single B tile: 32 k-rows x 16 chunks, row stride 272 B
#pragma unroll
            for (int i = 0; i < 2; i++) {
                int q = i * 256 + tid; int r = q >> 4, c = q & 15;
                uint32_t d = (uint32_t)(r * 272 + c * 16);
                cp16(bb + d, Bgh + (size_t)(kt + r) * ldB + n0 + c * 8);
            }
        }
        cp_commit();
    };

    issue(0, 0); issue(1, 32);

    // per-thread A row byte bases
    int rowA[4];
#pragma unroll
    for (int mt = 0; mt < 4; mt++) rowA[mt] = (wm * 64 + mt * 16 + ly) * 80 + 4 * lx;
    int rowB[4];
#pragma unroll
    for (int nt = 0; nt < 4; nt++) {
        if (!BK) rowB[nt] = (wn * 32 + nt * 8 + ly) * 80 + 4 * lx;
        else     rowB[nt] = wn * 32 + nt * 8 + ly;   // column index
    }

#pragma unroll 1
    for (int it = 0; it < nst; it++) {
        if (it + 1 < nst) cp_wait<1>();
        else              cp_wait<0>();
        __syncthreads();
        const char* S0 = sm + (it & 1) * STG;
        const char* A0t = S0;
        const char* A1t = S0 + 10240;                  // SPLITA only
        const char* B0t = S0 + OFF_B0;
        const char* B1t = S0 + OFF_B0 + 10240;         // SPLITB only

#pragma unroll
        for (int ks = 0; ks < 2; ks++) {
            const int kb = ks * 32;                 // byte offset of k16 slice (16 halfs)
            uint32_t a0[4][4], a1[4][4];
#pragma unroll
            for (int mt = 0; mt < 4; mt++) {
                int o = rowA[mt] + kb;
                a0[mt][0] = lds32(A0t, o);        a0[mt][1] = lds32(A0t, o + 640);
                a0[mt][2] = lds32(A0t, o + 16);   a0[mt][3] = lds32(A0t, o + 656);
                if (SPLITA) {
                    a1[mt][0] = lds32(A1t, o);        a1[mt][1] = lds32(A1t, o + 640);
                    a1[mt][2] = lds32(A1t, o + 16);   a1[mt][3] = lds32(A1t, o + 656);
                }
            }
            uint32_t b0[4][2], b1[4][2];
#pragma unroll
            for (int nt = 0; nt < 4; nt++) {
                if (!BK) {
                    int o = rowB[nt] + kb;
                    b0[nt][0] = lds32(B0t, o); b0[nt][1] = lds32(B0t, o + 16);
                    if (SPLITB) {
                        b1[nt][0] = lds32(B1t, o); b1[nt][1] = lds32(B1t, o + 16);
                    }
                } else {
                    int krow = (kb >> 1) + 2 * lx;        // k index = ks*16 + 2lx
                    int base0 = krow * 272 + rowB[nt] * 2;
                    b0[nt][0] = lds16x2(B0t, base0,        base0 + 272);
                    b0[nt][1] = lds16x2(B0t, base0 + 2176, base0 + 2448);
                }
            }
#pragma unroll
            for (int mt = 0; mt < 4; mt++)
#pragma unroll
                for (int nt = 0; nt < 4; nt++) {
                    mma16(acc[mt][nt], a0[mt], b0[nt]);
                    if (SPLITB) mma16(acc[mt][nt], a0[mt], b1[nt]);
                    if (SPLITA) mma16(acc[mt][nt], a1[mt], b0[nt]);
                }
        }
        __syncthreads();
        if (it + 2 < nst) issue(it & 1, (it + 2) * 32);
    }

    // ---- epilogue ----
    if (MODE == 2) {
        // per-row (within CTA) tile max via smem atomicMax, then shifted fp16 store
        __syncthreads();
        unsigned* rmax = (unsigned*)sm;
        if (tid < 128) rmax[tid] = 0u;     // f2o-encoded -inf lower bound
        __syncthreads();
#pragma unroll
        for (int mt = 0; mt < 4; mt++) {
#pragma unroll
            for (int hf = 0; hf < 2; hf++) {
                const int rl = wm * 64 + mt * 16 + ly + hf * 8;
                float mx = -INFINITY;
#pragma unroll
                for (int nt = 0; nt < 4; nt++) {
                    const int col = n0 + wn * 32 + nt * 8 + 2 * lx;
                    float x0 = acc[mt][nt][hf * 2 + 0] + auxz[col];
                    float x1 = acc[mt][nt][hf * 2 + 1] + auxz[col + 1];
                    mx = fmaxf(mx, fmaxf(x0, x1));
                }
                atomicMax(&rmax[rl], f2o(mx));
            }
        }
        __syncthreads();
        __half* S16o = (__half*)out0v;
        float*  Tmxo = (float*)out1v;
#pragma unroll
        for (int mt = 0; mt < 4; mt++) {
#pragma unroll
            for (int hf = 0; hf < 2; hf++) {
                const int rl = wm * 64 + mt * 16 + ly + hf * 8;
                const float m = o2f(rmax[rl]);
                const int gm = m0 + rl;
#pragma unroll
                for (int nt = 0; nt < 4; nt++) {
                    const int col = n0 + wn * 32 + nt * 8 + 2 * lx;
                    float x0 = acc[mt][nt][hf * 2 + 0] + auxz[col];
                    float x1 = acc[mt][nt][hf * 2 + 1] + auxz[col + 1];
                    *(__half2*)(S16o + (size_t)z * sOz + (size_t)gm * ldO + col) =
                        __floats2half2_rn(x0 - m, x1 - m);
                }
                if (wn == 0 && lx == 0)
                    Tmxo[((size_t)z * SQL + gm) * 16 + (n0 >> 7)] = m;
            }
        }
        return;
    }

#pragma unroll
    for (int mt = 0; mt < 4; mt++) {
#pragma unroll
        for (int hf = 0; hf < 2; hf++) {
            const int gm = m0 + wm * 64 + mt * 16 + ly + hf * 8;
#pragma unroll
            for (int nt = 0; nt < 4; nt++) {
                const int col = n0 + wn * 32 + nt * 8 + 2 * lx;
                float c0 = acc[mt][nt][hf * 2 + 0];
                float c1 = acc[mt][nt][hf * 2 + 1];
                if (MODE == 0) {
                    float x0 = c0 + auxz[col], x1 = c1 + auxz[col + 1];
                    __half h0 = __float2half_rn(x0), h1 = __float2half_rn(x1);
                    __half l0 = __float2half_rn(x0 - __half2float(h0));
                    __half l1 = __float2half_rn(x1 - __half2float(h1));
                    *(__half2*)((__half*)out0v + (size_t)z * sOz + (size_t)gm * ldO + col) =
                        __halves2half2(h0, h1);
                    *(__half2*)((__half*)out1v + (size_t)z * sO1z + (size_t)gm * ldO + col) =
                        __halves2half2(l0, l1);
                } else if (MODE == 1) {
                    float x0 = tanhf(c0 + auxz[col]), x1 = tanhf(c1 + auxz[col + 1]);
                    *(__half2*)((__half*)out0v + (size_t)gm * ldO + col) =
                        __halves2half2(__float2half_rn(x0), __float2half_rn(x1));
                } else {
                    *(float2*)((float*)out0v + (size_t)z * sOz + (size_t)gm * ldO + col) =
                        make_float2(c0, c1);
                }
            }
        }
    }
}

// ------------- softmax: read fp16 tile-shifted S + f32 tile max, write fp16 P -------------
__global__ __launch_bounds__(256)
void softmax_rows(const __half* __restrict__ S16, const float* __restrict__ Tmax,
                  __half* __restrict__ P0)
{
    const size_t row = blockIdx.x;
    const __half2* srow = (const __half2*)(S16 + row * SKL);
    __half2* prow = (__half2*)(P0 + row * SKL);
    const float* tmr = Tmax + row * 16;
    const int t = threadIdx.x;

    float m = -INFINITY;
#pragma unroll
    for (int i = 0; i < 16; i += 4) {
        float4 tv = *(const float4*)(tmr + i);
        m = fmaxf(m, fmaxf(fmaxf(tv.x, tv.y), fmaxf(tv.z, tv.w)));
    }

    const int tg = t >> 6;
    float e[4][2];
    float sum = 0.f;
#pragma unroll
    for (int i = 0; i < 4; i++) {
        float adj = tmr[tg + 4 * i] - m;
        __half2 sv = srow[t + i * 256];
        float s0 = __low2float(sv)  + adj;
        float s1 = __high2float(sv) + adj;
        e[i][0] = __expf(s0); e[i][1] = __expf(s1);
        sum += e[i][0] + e[i][1];
    }

#pragma unroll
    for (int o = 16; o > 0; o >>= 1) sum += __shfl_xor_sync(0xFFFFFFFFu, sum, o);
    __shared__ float red[8];
    if ((t & 31) == 0) red[t >> 5] = sum;
    __syncthreads();
    float tot = 0.f;
#pragma unroll
    for (int w = 0; w < 8; w++) tot += red[w];
    const float inv = 1.0f / tot;

#pragma unroll
    for (int i = 0; i < 4; i++)
        prow[t + i * 256] = __floats2half2_rn(e[i][0] * inv, e[i][1] * inv);
}

// ---------------- launch ----------------
extern "C" void kernel_launch(void* const* d_in, const int* in_sizes, int n_in,
                              void* d_out, int out_size)
{
    const float* q    = (const float*)d_in[0];
    const float* k    = (const float*)d_in[1];
    const float* v    = (const float*)d_in[2];
    const void*  mask = d_in[3];
    const float* Wq   = (const float*)d_in[4];
    const float* bq   = (const float*)d_in[5];
    const float* Wk   = (const float*)d_in[6];
    const float* bk   = (const float*)d_in[7];
    const float* Wv   = (const float*)d_in[8];
    const float* bvp  = (const float*)d_in[9];
    float* out        = (float*)d_out;

    __half *q0, *q1, *k0, *k1, *v0;
    __half *Wq0, *Wq1, *Wk0, *Wk1, *Wv0;
    __half *Qp0, *Qp1, *Kp0, *Kp1, *Vp0, *P0, *S16;
    float *Tmax, *maskf;
    cudaGetSymbolAddress((void**)&q0, g_q0);   cudaGetSymbolAddress((void**)&q1, g_q1);
    cudaGetSymbolAddress((void**)&k0, g_k0);   cudaGetSymbolAddress((void**)&k1, g_k1);
    cudaGetSymbolAddress((void**)&v0, g_v0);
    cudaGetSymbolAddress((void**)&Wq0, g_Wq0); cudaGetSymbolAddress((void**)&Wq1, g_Wq1);
    cudaGetSymbolAddress((void**)&Wk0, g_Wk0); cudaGetSymbolAddress((void**)&Wk1, g_Wk1);
    cudaGetSymbolAddress((void**)&Wv0, g_Wv0);
    cudaGetSymbolAddress((void**)&Qp0, g_Qp0); cudaGetSymbolAddress((void**)&Qp1, g_Qp1);
    cudaGetSymbolAddress((void**)&Kp0, g_Kp0); cudaGetSymbolAddress((void**)&Kp1, g_Kp1);
    cudaGetSymbolAddress((void**)&Vp0, g_Vp0);
    cudaGetSymbolAddress((void**)&P0, g_P0);
    cudaGetSymbolAddress((void**)&S16, g_S16); cudaGetSymbolAddress((void**)&Tmax, g_Tmax);
    cudaGetSymbolAddress((void**)&maskf, g_maskf);

    // mask -> float
    detect_mask_kernel<<<1, 256>>>((const unsigned int*)mask);
    convert_mask_kernel<<<(BATCH * SKL + 255) / 256, 256>>>(mask, BATCH * SKL);

    // q/k split + v convert, single launch, packed uint2 stores
    {
        int n4 = (int)(NELEM / 4);
        int nb = (n4 + 255) / 256;
        dim3 g3(nb, 3);
        prep_inputs_kernel<<<g3, 256>>>((const float4*)q, (const float4*)k,
                                        (const float4*)v,
                                        (uint2*)q0, (uint2*)q1,
                                        (uint2*)k0, (uint2*)k1,
                                        (uint2*)v0, n4);
    }
    // transpose + split all three weights in one launch
    {
        dim3 g(DIM / 32, DIM / 32, 3);
        transpose_split3_kernel<<<g, 256>>>(Wq, Wk, Wv, Wq0, Wq1, Wk0, Wk1, Wv0);
    }

    const int SMEM02 = 2 * 40960;   // modes 0,2: 81920 B -> 2 CTAs/SM
    const int SMEM1  = 2 * 20480;   // mode 1:   40960 B
    const int SMEM3  = 2 * 18944;   // mode 3:   37888 B
    cudaFuncSetAttribute(mma_gemm<0>, cudaFuncAttributeMaxDynamicSharedMemorySize, SMEM02);
    cudaFuncSetAttribute(mma_gemm<1>, cudaFuncAttributeMaxDynamicSharedMemorySize, SMEM1);
    cudaFuncSetAttribute(mma_gemm<2>, cudaFuncAttributeMaxDynamicSharedMemorySize, SMEM02);
    cudaFuncSetAttribute(mma_gemm<3>, cudaFuncAttributeMaxDynamicSharedMemorySize, SMEM3);

    // Q & K projections MERGED: grid z=2 selects problem instance via pointer-diff strides
    {
        dim3 grid(DIM / 128, (BATCH * SQL) / 128, 2);
        long long sAz   = (long long)(k0  - q0);
        long long sAlz  = (long long)(k1  - q1);
        long long sBz   = (long long)(Wk0 - Wq0);
        long long sBlz  = (long long)(Wk1 - Wq1);
        long long sAuxz = (long long)(bk  - bq);
        long long sOz   = (long long)(Kp0 - Qp0);
        long long sO1z  = (long long)(Kp1 - Qp1);
        mma_gemm<0><<<grid, 256, SMEM02>>>(q0, q1, Wq0, Wq1, bq, Qp0, Qp1,
                                           DIM, DIM,
                                           sAz, sAlz, sBz, sBlz, sAuxz,
                                           DIM, DIM, sOz, sO1z);
    }
    // V projection: single product v0 @ Wv0^T
    {
        dim3 grid(DIM / 128, (BATCH * SQL) / 128, 1);
        mma_gemm<1><<<grid, 256, SMEM1>>>(v0, v0, Wv0, Wv0, bvp, Vp0, nullptr,
                                          DIM, DIM, 0, 0, 0, 0, 0,
                                          DIM, DIM, 0, 0);
    }

    // S16 = tile-shifted fp16 (Qp @ Kp^T + mask), Tmax = per-row tile maxes
    {
        dim3 grid(SKL / 128, SQL / 128, BATCH);
        mma_gemm<2><<<grid, 256, SMEM02>>>(Qp0, Qp1, Kp0, Kp1, maskf, S16, Tmax,
                                           DIM, DIM,
                                           (long long)SQL * DIM, (long long)SQL * DIM,
                                           (long long)SKL * DIM, (long long)SKL * DIM,
                                           SKL,
                                           DIM, SKL, (long long)SQL * SKL, 0);
    }

    // softmax rows -> single fp16 P
    softmax_rows<<<BATCH * SQL, 256>>>(S16, Tmax, P0);

    // out = P0 @ Vp0  (batched, single product)
    {
        dim3 grid(DIM / 128, SQL / 128, BATCH);
        mma_gemm<3><<<grid, 256, SMEM3>>>(P0, P0, Vp0, Vp0, nullptr, out, nullptr,
                                          SKL, DIM,
                                          (long long)SQL * SKL, (long long)SQL * SKL,
                                          (long long)SKL * DIM, (long long)SKL * DIM,
                                          0,
                                          SKL, DIM, (long long)SQL * DIM, 0);
    }
}

// round 17
// speedup vs baseline: 1.2063x; 1.0046x over previous
#include <cuda_runtime.h>
#include <cuda_fp16.h>
#include <cstdint>
#include <math.h>

// Problem dims
#define BATCH 8
#define SQL   2048
#define SKL   2048
#define DIM   1024

#define NELEM ((size_t)BATCH * SQL * DIM)      // 16.8M elements

// ---------------- device scratch (static) ----------------
__device__ __half g_q0[NELEM], g_q1[NELEM];
__device__ __half g_k0[NELEM], g_k1[NELEM];
__device__ __half g_v0[NELEM];                      // V input single fp16
__device__ __half g_Wq0[DIM*DIM], g_Wq1[DIM*DIM];   // transposed [N][K]
__device__ __half g_Wk0[DIM*DIM], g_Wk1[DIM*DIM];
__device__ __half g_Wv0[DIM*DIM];                   // WvT single fp16
__device__ __half g_Qp0[NELEM], g_Qp1[NELEM];
__device__ __half g_Kp0[NELEM], g_Kp1[NELEM];
__device__ __half g_Vp0[NELEM];                     // single fp16 V
__device__ __half g_S16[(size_t)BATCH * SQL * SKL]; // tile-shifted scores (fp16)
__device__ float  g_Tmax[(size_t)BATCH * SQL * 16]; // per-row per-tile max (f32)
__device__ __half g_P0[(size_t)BATCH * SQL * SKL];  // softmax P (single fp16)
__device__ float  g_maskf[BATCH * SKL];
__device__ int    g_mask_mode;

// ---------------- small helpers ----------------
__device__ __forceinline__ uint32_t smem_u32(const void* p) {
    uint32_t a;
    asm("{ .reg .u64 t; cvta.to.shared.u64 t, %1; cvt.u32.u64 %0, t; }" : "=r"(a) : "l"(p));
    return a;
}
__device__ __forceinline__ void cp16(uint32_t dst, const void* src) {
    asm volatile("cp.async.cg.shared.global [%0], [%1], 16;" :: "r"(dst), "l"(src) : "memory");
}
__device__ __forceinline__ void cp_commit() {
    asm volatile("cp.async.commit_group;" ::: "memory");
}
template<int N> __device__ __forceinline__ void cp_wait() {
    asm volatile("cp.async.wait_group %0;" :: "n"(N) : "memory");
}
// mma.sync m16n8k16 f16 -> f32 accum
__device__ __forceinline__ void mma16(float* c, const uint32_t* a, const uint32_t* b) {
    asm volatile(
        "mma.sync.aligned.m16n8k16.row.col.f32.f16.f16.f32 "
        "{%0,%1,%2,%3}, {%4,%5,%6,%7}, {%8,%9}, {%0,%1,%2,%3};"
        : "+f"(c[0]), "+f"(c[1]), "+f"(c[2]), "+f"(c[3])
        : "r"(a[0]), "r"(a[1]), "r"(a[2]), "r"(a[3]), "r"(b[0]), "r"(b[1]));
}
__device__ __forceinline__ uint32_t lds32(const char* smem, int off) {
    return *(const uint32_t*)(smem + off);
}
__device__ __forceinline__ uint32_t lds16x2(const char* smem, int off_lo, int off_hi) {
    uint32_t lo = *(const uint16_t*)(smem + off_lo);
    uint32_t hi = *(const uint16_t*)(smem + off_hi);
    return lo | (hi << 16);
}
// float <-> monotonic unsigned encoding (for atomicMax on floats incl. negatives)
__device__ __forceinline__ unsigned f2o(float f) {
    unsigned u = __float_as_uint(f);
    return (u & 0x80000000u) ? ~u : (u | 0x80000000u);
}
__device__ __forceinline__ float o2f(unsigned u) {
    return (u & 0x80000000u) ? __uint_as_float(u & 0x7FFFFFFFu) : __uint_as_float(~u);
}
__device__ __forceinline__ uint32_t h2u(__half2 h) { return *(uint32_t*)&h; }

// ---------------- mask dtype sniffing (verified R1) ----------------
__global__ void detect_mask_kernel(const unsigned int* __restrict__ w)
{
    __shared__ unsigned int f;
    if (threadIdx.x == 0) f = 0u;
    __syncthreads();
    unsigned int loc = 0u;
    for (int i = threadIdx.x; i < 4096; i += 256) {
        unsigned int x = w[i];
        if (x == 0x3F803F80u || x == 0x00003F80u) loc |= 8u;
        if (x == 0x3F800000u)                     loc |= 4u;
        if (x > 1u)                               loc |= 2u;
    }
    atomicOr(&f, loc);
    __syncthreads();
    if (threadIdx.x == 0) {
        unsigned int ff = f;
        g_mask_mode = (ff & 8u) ? 3 : (ff & 4u) ? 2 : (ff & 2u) ? 1 : 0;
    }
}
__global__ void convert_mask_kernel(const void* __restrict__ m, int n)
{
    int i = blockIdx.x * blockDim.x + threadIdx.x;
    if (i >= n) return;
    int mode = g_mask_mode;
    float v;
    if (mode == 0)      v = (float)((const int*)m)[i];
    else if (mode == 1) v = (float)((const unsigned char*)m)[i];
    else if (mode == 2) v = ((const float*)m)[i];
    else {
        unsigned short h = ((const unsigned short*)m)[i];
        v = __uint_as_float(((unsigned int)h) << 16);
    }
    g_maskf[i] = v;
}

// ------- q/k split + v convert, ONE launch, 32 B/thread, uint4 stores -------
__global__ __launch_bounds__(256)
void prep_inputs_kernel(const float4* __restrict__ sq, const float4* __restrict__ sk,
                        const float4* __restrict__ sv,
                        uint4* __restrict__ q0, uint4* __restrict__ q1,
                        uint4* __restrict__ k0, uint4* __restrict__ k1,
                        uint4* __restrict__ v0, int n8)
{
    int i = blockIdx.x * blockDim.x + threadIdx.x;
    if (i >= n8) return;
    if (blockIdx.y == 2) {
        float4 xa = sv[2*i], xb = sv[2*i + 1];
        uint4 o;
        o.x = h2u(__halves2half2(__float2half_rn(xa.x), __float2half_rn(xa.y)));
        o.y = h2u(__halves2half2(__float2half_rn(xa.z), __float2half_rn(xa.w)));
        o.z = h2u(__halves2half2(__float2half_rn(xb.x), __float2half_rn(xb.y)));
        o.w = h2u(__halves2half2(__float2half_rn(xb.z), __float2half_rn(xb.w)));
        v0[i] = o;
        return;
    }
    const float4* src = blockIdx.y ? sk : sq;
    uint4* h0 = blockIdx.y ? k0 : q0;
    uint4* h1 = blockIdx.y ? k1 : q1;
    float4 xa = src[2*i], xb = src[2*i + 1];
    float f[8] = {xa.x, xa.y, xa.z, xa.w, xb.x, xb.y, xb.z, xb.w};
    __half h[8], l[8];
#pragma unroll
    for (int j = 0; j < 8; j++) {
        h[j] = __float2half_rn(f[j]);
        l[j] = __float2half_rn(f[j] - __half2float(h[j]));
    }
    uint4 oh, ol;
    oh.x = h2u(__halves2half2(h[0], h[1])); oh.y = h2u(__halves2half2(h[2], h[3]));
    oh.z = h2u(__halves2half2(h[4], h[5])); oh.w = h2u(__halves2half2(h[6], h[7]));
    ol.x = h2u(__halves2half2(l[0], l[1])); ol.y = h2u(__halves2half2(l[2], l[3]));
    ol.z = h2u(__halves2half2(l[4], l[5])); ol.w = h2u(__halves2half2(l[6], l[7]));
    h0[i] = oh;
    h1[i] = ol;
}

// W [K,N] -> WT [N,K]: z=0,1 -> split (Wq,Wk); z=2 -> plain single (Wv)
__global__ __launch_bounds__(256)
void transpose_split3_kernel(const float* __restrict__ Wa, const float* __restrict__ Wb,
                             const float* __restrict__ Wc,
                             __half* __restrict__ A0, __half* __restrict__ A1,
                             __half* __restrict__ B0, __half* __restrict__ B1,
                             __half* __restrict__ C0)
{
    const float* W = (blockIdx.z == 0) ? Wa : (blockIdx.z == 1) ? Wb : Wc;
    __shared__ float t[32][33];
    int n0 = blockIdx.x * 32, k0 = blockIdx.y * 32;
    int tx = threadIdx.x & 31, ty = threadIdx.x >> 5;
    for (int r = ty; r < 32; r += 8)
        t[r][tx] = W[(size_t)(k0 + r) * DIM + n0 + tx];
    __syncthreads();
    if (blockIdx.z < 2) {
        __half* T0 = (blockIdx.z == 0) ? A0 : B0;
        __half* T1 = (blockIdx.z == 0) ? A1 : B1;
        for (int r = ty; r < 32; r += 8) {
            float x = t[tx][r];
            __half h = __float2half_rn(x);
            size_t o = (size_t)(n0 + r) * DIM + k0 + tx;
            T0[o] = h; T1[o] = __float2half_rn(x - __half2float(h));
        }
    } else {
        for (int r = ty; r < 32; r += 8) {
            float x = t[tx][r];
            C0[(size_t)(n0 + r) * DIM + k0 + tx] = __float2half_rn(x);
        }
    }
}

// ------------- fp16 mma GEMM: 128x128 tile, Kc=32, 2-stage cp.async, 2 CTAs/SM ----
// MODE 0: C = A@B^T + bias      -> fp16 split write   (Q&K proj MERGED via z, 3 prod)
// MODE 1: C = tanh(A@B^T+bias)  -> fp16 write         (V proj, SINGLE product)
// MODE 2: C = A@B^T + mask      -> tile-shifted fp16 S + f32 tile max (QK^T, 3 prod)
// MODE 3: C = A0@B0 (B=[K][N])  -> f32 write          (P@V, single product)
template<int MODE>
__global__ __launch_bounds__(256, 2)
void mma_gemm(const __half* __restrict__ Ah, const __half* __restrict__ Al,
              const __half* __restrict__ Bh, const __half* __restrict__ Bl,
              const float* __restrict__ aux,
              void* __restrict__ out0v, void* __restrict__ out1v,
              int ldA, int ldB,
              long long sAz, long long sAlz, long long sBz, long long sBlz,
              long long sAuxz,
              int nK, int ldO, long long sOz, long long sO1z)
{
    constexpr bool BK     = (MODE == 3);                 // B is [K][N]
    constexpr bool SPLITA = (MODE == 0 || MODE == 2);
    constexpr bool SPLITB = (MODE == 0 || MODE == 2);
    constexpr int  OFF_B0 = SPLITA ? 20480 : 10240;
    constexpr int  STG    = BK ? (10240 + 8704)
                               : (OFF_B0 + (SPLITB ? 20480 : 10240));

    extern __shared__ char sm[];
    const uint32_t sb = smem_u32(sm);
    const int tid = threadIdx.x;
    const int lid = tid & 31, wid = tid >> 5;
    const int wm = wid >> 2, wn = wid & 3;      // 2 x 4 warp grid, warp tile 64x32
    const int lx = lid & 3,  ly = lid >> 2;
    const int m0 = blockIdx.y * 128, n0 = blockIdx.x * 128, z = blockIdx.z;
    const int nst = nK / 32;

    const __half* Agh = Ah + (size_t)z * sAz;
    const __half* Agl = Al + (size_t)z * sAlz;
    const __half* Bgh = Bh + (size_t)z * sBz;
    const __half* Bgl = Bl + (size_t)z * sBlz;
    const float*  auxz = aux + (size_t)z * sAuxz;

    float acc[4][4][4];
#pragma unroll
    for (int a = 0; a < 4; a++)
#pragma unroll
        for (int b = 0; b < 4; b++)
#pragma unroll
            for (int c = 0; c < 4; c++) acc[a][b][c] = 0.f;

    // ---- producer: fill stage SLOT st with k-chunk kt (32 k) ----
    auto issue = [&](int st, int kt) {
        uint32_t base = sb + (uint32_t)st * STG;
        // A tile(s): 128 rows x 4 chunks (16B = 8 halfs), row stride 80 B
#pragma unroll
        for (int i = 0; i < 2; i++) {
            int q = i * 256 + tid; int r = q >> 2, c = q & 3;
            uint32_t d = (uint32_t)(r * 80 + c * 16);
            cp16(base + d, Agh + (size_t)(m0 + r) * ldA + kt + c * 8);
            if (SPLITA) cp16(base + 10240 + d, Agl + (size_t)(m0 + r) * ldA + kt + c * 8);
        }
        uint32_t bb = base + OFF_B0;
        if (!BK) {
#pragma unroll
            for (int i = 0; i < 2; i++) {
                int q = i * 256 + tid; int r = q >> 2, c = q & 3;
                uint32_t d = (uint32_t)(r * 80 + c * 16);
                cp16(bb + d, Bgh + (size_t)(n0 + r) * ldB + kt + c * 8);
                if (SPLITB) cp16(bb + 10240 + d, Bgl + (size_t)(n0 + r) * ldB + kt + c * 8);
            }
        } else {
            // single B tile: 32 k-rows x 16 chunks, row stride 272 B
#pragma unroll
            for (int i = 0; i < 2; i++) {
                int q = i * 256 + tid; int r = q >> 4, c = q & 15;
                uint32_t d = (uint32_t)(r * 272 + c * 16);
                cp16(bb + d, Bgh + (size_t)(kt + r) * ldB + n0 + c * 8);
            }
        }
        cp_commit();
    };

    issue(0, 0); issue(1, 32);

    // per-thread A row byte bases
    int rowA[4];
#pragma unroll
    for (int mt = 0; mt < 4; mt++) rowA[mt] = (wm * 64 + mt * 16 + ly) * 80 + 4 * lx;
    int rowB[4];
#pragma unroll
    for (int nt = 0; nt < 4; nt++) {
        if (!BK) rowB[nt] = (wn * 32 + nt * 8 + ly) * 80 + 4 * lx;
        else     rowB[nt] = wn * 32 + nt * 8 + ly;   // column index
    }

#pragma unroll 1
    for (int it = 0; it < nst; it++) {
        if (it + 1 < nst) cp_wait<1>();
        else              cp_wait<0>();
        __syncthreads();
        const char* S0 = sm + (it & 1) * STG;
        const char* A0t = S0;
        const char* A1t = S0 + 10240;                  // SPLITA only
        const char* B0t = S0 + OFF_B0;
        const char* B1t = S0 + OFF_B0 + 10240;         // SPLITB only

#pragma unroll
        for (int ks = 0; ks < 2; ks++) {
            const int kb = ks * 32;                 // byte offset of k16 slice (16 halfs)
            uint32_t a0[4][4], a1[4][4];
#pragma unroll
            for (int mt = 0; mt < 4; mt++) {
                int o = rowA[mt] + kb;
                a0[mt][0] = lds32(A0t, o);        a0[mt][1] = lds32(A0t, o + 640);
                a0[mt][2] = lds32(A0t, o + 16);   a0[mt][3] = lds32(A0t, o + 656);
                if (SPLITA) {
                    a1[mt][0] = lds32(A1t, o);        a1[mt][1] = lds32(A1t, o + 640);
                    a1[mt][2] = lds32(A1t, o + 16);   a1[mt][3] = lds32(A1t, o + 656);
                }
            }
            uint32_t b0[4][2], b1[4][2];
#pragma unroll
            for (int nt = 0; nt < 4; nt++) {
                if (!BK) {
                    int o = rowB[nt] + kb;
                    b0[nt][0] = lds32(B0t, o); b0[nt][1] = lds32(B0t, o + 16);
                    if (SPLITB) {
                        b1[nt][0] = lds32(B1t, o); b1[nt][1] = lds32(B1t, o + 16);
                    }
                } else {
                    int krow = (kb >> 1) + 2 * lx;        // k index = ks*16 + 2lx
                    int base0 = krow * 272 + rowB[nt] * 2;
                    b0[nt][0] = lds16x2(B0t, base0,        base0 + 272);
                    b0[nt][1] = lds16x2(B0t, base0 + 2176, base0 + 2448);
                }
            }
#pragma unroll
            for (int mt = 0; mt < 4; mt++)
#pragma unroll
                for (int nt = 0; nt < 4; nt++) {
                    mma16(acc[mt][nt], a0[mt], b0[nt]);
                    if (SPLITB) mma16(acc[mt][nt], a0[mt], b1[nt]);
                    if (SPLITA) mma16(acc[mt][nt], a1[mt], b0[nt]);
                }
        }
        __syncthreads();
        if (it + 2 < nst) issue(it & 1, (it + 2) * 32);
    }

    // ---- epilogue ----
    if (MODE == 2) {
        // per-row (within CTA) tile max via smem atomicMax, then shifted fp16 store
        __syncthreads();
        unsigned* rmax = (unsigned*)sm;
        if (tid < 128) rmax[tid] = 0u;     // f2o-encoded -inf lower bound
        __syncthreads();
#pragma unroll
        for (int mt = 0; mt < 4; mt++) {
#pragma unroll
            for (int hf = 0; hf < 2; hf++) {
                const int rl = wm * 64 + mt * 16 + ly + hf * 8;
                float mx = -INFINITY;
#pragma unroll
                for (int nt = 0; nt < 4; nt++) {
                    const int col = n0 + wn * 32 + nt * 8 + 2 * lx;
                    float x0 = acc[mt][nt][hf * 2 + 0] + auxz[col];
                    float x1 = acc[mt][nt][hf * 2 + 1] + auxz[col + 1];
                    mx = fmaxf(mx, fmaxf(x0, x1));
                }
                atomicMax(&rmax[rl], f2o(mx));
            }
        }
        __syncthreads();
        __half* S16o = (__half*)out0v;
        float*  Tmxo = (float*)out1v;
#pragma unroll
        for (int mt = 0; mt < 4; mt++) {
#pragma unroll
            for (int hf = 0; hf < 2; hf++) {
                const int rl = wm * 64 + mt * 16 + ly + hf * 8;
                const float m = o2f(rmax[rl]);
                const int gm = m0 + rl;
#pragma unroll
                for (int nt = 0; nt < 4; nt++) {
                    const int col = n0 + wn * 32 + nt * 8 + 2 * lx;
                    float x0 = acc[mt][nt][hf * 2 + 0] + auxz[col];
                    float x1 = acc[mt][nt][hf * 2 + 1] + auxz[col + 1];
                    *(__half2*)(S16o + (size_t)z * sOz + (size_t)gm * ldO + col) =
                        __floats2half2_rn(x0 - m, x1 - m);
                }
                if (wn == 0 && lx == 0)
                    Tmxo[((size_t)z * SQL + gm) * 16 + (n0 >> 7)] = m;
            }
        }
        return;
    }

#pragma unroll
    for (int mt = 0; mt < 4; mt++) {
#pragma unroll
        for (int hf = 0; hf < 2; hf++) {
            const int gm = m0 + wm * 64 + mt * 16 + ly + hf * 8;
#pragma unroll
            for (int nt = 0; nt < 4; nt++) {
                const int col = n0 + wn * 32 + nt * 8 + 2 * lx;
                float c0 = acc[mt][nt][hf * 2 + 0];
                float c1 = acc[mt][nt][hf * 2 + 1];
                if (MODE == 0) {
                    float x0 = c0 + auxz[col], x1 = c1 + auxz[col + 1];
                    __half h0 = __float2half_rn(x0), h1 = __float2half_rn(x1);
                    __half l0 = __float2half_rn(x0 - __half2float(h0));
                    __half l1 = __float2half_rn(x1 - __half2float(h1));
                    *(__half2*)((__half*)out0v + (size_t)z * sOz + (size_t)gm * ldO + col) =
                        __halves2half2(h0, h1);
                    *(__half2*)((__half*)out1v + (size_t)z * sO1z + (size_t)gm * ldO + col) =
                        __halves2half2(l0, l1);
                } else if (MODE == 1) {
                    float x0 = tanhf(c0 + auxz[col]), x1 = tanhf(c1 + auxz[col + 1]);
                    *(__half2*)((__half*)out0v + (size_t)gm * ldO + col) =
                        __halves2half2(__float2half_rn(x0), __float2half_rn(x1));
                } else {
                    *(float2*)((float*)out0v + (size_t)z * sOz + (size_t)gm * ldO + col) =
                        make_float2(c0, c1);
                }
            }
        }
    }
}

// ---- softmax: one float4 (8 halfs, same tile) per thread, float4 out ----
__global__ __launch_bounds__(256)
void softmax_rows(const __half* __restrict__ S16, const float* __restrict__ Tmax,
                  __half* __restrict__ P0)
{
    const size_t row = blockIdx.x;
    const float4* srow = (const float4*)(S16 + row * SKL);   // 256 float4 per row
    float4* prow = (float4*)(P0 + row * SKL);
    const float* tmr = Tmax + row * 16;
    const int t = threadIdx.x;

    // global row max from the 16 tile maxes
    float m = -INFINITY;
#pragma unroll
    for (int i = 0; i < 16; i += 4) {
        float4 tv = *(const float4*)(tmr + i);
        m = fmaxf(m, fmaxf(fmaxf(tv.x, tv.y), fmaxf(tv.z, tv.w)));
    }

    // thread t covers halfs [8t, 8t+8) -> all within tile t>>4
    const float adj = tmr[t >> 4] - m;
    float4 sv = srow[t];
    const __half2* hp = (const __half2*)&sv;
    float e[8];
    float sum = 0.f;
#pragma unroll
    for (int i = 0; i < 4; i++) {
        e[2*i]   = __expf(__low2float(hp[i])  + adj);
        e[2*i+1] = __expf(__high2float(hp[i]) + adj);
        sum += e[2*i] + e[2*i+1];
    }

#pragma unroll
    for (int o = 16; o > 0; o >>= 1) sum += __shfl_xor_sync(0xFFFFFFFFu, sum, o);
    __shared__ float red[8];
    if ((t & 31) == 0) red[t >> 5] = sum;
    __syncthreads();
    float tot = 0.f;
#pragma unroll
    for (int w = 0; w < 8; w++) tot += red[w];
    const float inv = 1.0f / tot;

    float4 ov;
    __half2* op = (__half2*)&ov;
#pragma unroll
    for (int i = 0; i < 4; i++)
        op[i] = __floats2half2_rn(e[2*i] * inv, e[2*i+1] * inv);
    prow[t] = ov;
}

// ---------------- launch ----------------
extern "C" void kernel_launch(void* const* d_in, const int* in_sizes, int n_in,
                              void* d_out, int out_size)
{
    const float* q    = (const float*)d_in[0];
    const float* k    = (const float*)d_in[1];
    const float* v    = (const float*)d_in[2];
    const void*  mask = d_in[3];
    const float* Wq   = (const float*)d_in[4];
    const float* bq   = (const float*)d_in[5];
    const float* Wk   = (const float*)d_in[6];
    const float* bk   = (const float*)d_in[7];
    const float* Wv   = (const float*)d_in[8];
    const float* bvp  = (const float*)d_in[9];
    float* out        = (float*)d_out;

    __half *q0, *q1, *k0, *k1, *v0;
    __half *Wq0, *Wq1, *Wk0, *Wk1, *Wv0;
    __half *Qp0, *Qp1, *Kp0, *Kp1, *Vp0, *P0, *S16;
    float *Tmax, *maskf;
    cudaGetSymbolAddress((void**)&q0, g_q0);   cudaGetSymbolAddress((void**)&q1, g_q1);
    cudaGetSymbolAddress((void**)&k0, g_k0);   cudaGetSymbolAddress((void**)&k1, g_k1);
    cudaGetSymbolAddress((void**)&v0, g_v0);
    cudaGetSymbolAddress((void**)&Wq0, g_Wq0); cudaGetSymbolAddress((void**)&Wq1, g_Wq1);
    cudaGetSymbolAddress((void**)&Wk0, g_Wk0); cudaGetSymbolAddress((void**)&Wk1, g_Wk1);
    cudaGetSymbolAddress((void**)&Wv0, g_Wv0);
    cudaGetSymbolAddress((void**)&Qp0, g_Qp0); cudaGetSymbolAddress((void**)&Qp1, g_Qp1);
    cudaGetSymbolAddress((void**)&Kp0, g_Kp0); cudaGetSymbolAddress((void**)&Kp1, g_Kp1);
    cudaGetSymbolAddress((void**)&Vp0, g_Vp0);
    cudaGetSymbolAddress((void**)&P0, g_P0);
    cudaGetSymbolAddress((void**)&S16, g_S16); cudaGetSymbolAddress((void**)&Tmax, g_Tmax);
    cudaGetSymbolAddress((void**)&maskf, g_maskf);

    // mask -> float
    detect_mask_kernel<<<1, 256>>>((const unsigned int*)mask);
    convert_mask_kernel<<<(BATCH * SKL + 255) / 256, 256>>>(mask, BATCH * SKL);

    // q/k split + v convert, single launch, 32 B per thread
    {
        int n8 = (int)(NELEM / 8);
        int nb = (n8 + 255) / 256;
        dim3 g3(nb, 3);
        prep_inputs_kernel<<<g3, 256>>>((const float4*)q, (const float4*)k,
                                        (const float4*)v,
                                        (uint4*)q0, (uint4*)q1,
                                        (uint4*)k0, (uint4*)k1,
                                        (uint4*)v0, n8);
    }
    // transpose + split all three weights in one launch
    {
        dim3 g(DIM / 32, DIM / 32, 3);
        transpose_split3_kernel<<<g, 256>>>(Wq, Wk, Wv, Wq0, Wq1, Wk0, Wk1, Wv0);
    }

    const int SMEM02 = 2 * 40960;   // modes 0,2: 81920 B -> 2 CTAs/SM
    const int SMEM1  = 2 * 20480;   // mode 1:   40960 B
    const int SMEM3  = 2 * 18944;   // mode 3:   37888 B
    cudaFuncSetAttribute(mma_gemm<0>, cudaFuncAttributeMaxDynamicSharedMemorySize, SMEM02);
    cudaFuncSetAttribute(mma_gemm<1>, cudaFuncAttributeMaxDynamicSharedMemorySize, SMEM1);
    cudaFuncSetAttribute(mma_gemm<2>, cudaFuncAttributeMaxDynamicSharedMemorySize, SMEM02);
    cudaFuncSetAttribute(mma_gemm<3>, cudaFuncAttributeMaxDynamicSharedMemorySize, SMEM3);

    // Q & K projections MERGED: grid z=2 selects problem instance via pointer-diff strides
    {
        dim3 grid(DIM / 128, (BATCH * SQL) / 128, 2);
        long long sAz   = (long long)(k0  - q0);
        long long sAlz  = (long long)(k1  - q1);
        long long sBz   = (long long)(Wk0 - Wq0);
        long long sBlz  = (long long)(Wk1 - Wq1);
        long long sAuxz = (long long)(bk  - bq);
        long long sOz   = (long long)(Kp0 - Qp0);
        long long sO1z  = (long long)(Kp1 - Qp1);
        mma_gemm<0><<<grid, 256, SMEM02>>>(q0, q1, Wq0, Wq1, bq, Qp0, Qp1,
                                           DIM, DIM,
                                           sAz, sAlz, sBz, sBlz, sAuxz,
                                           DIM, DIM, sOz, sO1z);
    }
    // V projection: single product v0 @ Wv0^T
    {
        dim3 grid(DIM / 128, (BATCH * SQL) / 128, 1);
        mma_gemm<1><<<grid, 256, SMEM1>>>(v0, v0, Wv0, Wv0, bvp, Vp0, nullptr,
                                          DIM, DIM, 0, 0, 0, 0, 0,
                                          DIM, DIM, 0, 0);
    }

    // S16 = tile-shifted fp16 (Qp @ Kp^T + mask), Tmax = per-row tile maxes
    {
        dim3 grid(SKL / 128, SQL / 128, BATCH);
        mma_gemm<2><<<grid, 256, SMEM02>>>(Qp0, Qp1, Kp0, Kp1, maskf, S16, Tmax,
                                           DIM, DIM,
                                           (long long)SQL * DIM, (long long)SQL * DIM,
                                           (long long)SKL * DIM, (long long)SKL * DIM,
                                           SKL,
                                           DIM, SKL, (long long)SQL * SKL, 0);
    }

    // softmax rows -> single fp16 P
    softmax_rows<<<BATCH * SQL, 256>>>(S16, Tmax, P0);

    // out = P0 @ Vp0  (batched, single product)
    {
        dim3 grid(DIM / 128, SQL / 128, BATCH);
        mma_gemm<3><<<grid, 256, SMEM3>>>(P0, P0, Vp0, Vp0, nullptr, out, nullptr,
                                          SKL, DIM,
                                          (long long)SQL * SKL, (long long)SQL * SKL,
                                          (long long)SKL * DIM, (long long)SKL * DIM,
                                          0,
                                          SKL, DIM, (long long)SQL * DIM, 0);
    }
}